// round 9
// baseline (speedup 1.0000x reference)
#include <cuda_runtime.h>
#include <math.h>

#define TT 128
#define NB 256
#define EE 512
#define AD 8
#define HH 512
#define H3 1536
#define TN (TT*NB)
#define TNH ((size_t)TN*HH)
#define NH (NB*HH)
#define NCTA 128
#define NGROUP 8
#define GSIZE 16

// Scratch (no cudaMalloc allowed)
__device__ float g_gi [(size_t)TN * H3];   // input-side gates, cell 1 (+ b_ih + b_hh[r,z])
__device__ float g_gip[(size_t)TN * H3];   // input-side gates, cell 2
__device__ float g_A [2][2][NH];           // masked hidden state (k-permuted cols), parity buffer
struct __align__(128) Bar { unsigned cnt; unsigned gen; unsigned pad[30]; };
__device__ Bar g_bars[NGROUP];

__device__ __forceinline__ unsigned f2tf(float x) {
    unsigned r;
    asm("cvt.rna.tf32.f32 %0, %1;" : "=r"(r) : "f"(x));
    return r;
}

__device__ __forceinline__ void mma8(float* c, const unsigned* a, const unsigned* b) {
    asm volatile(
        "mma.sync.aligned.m16n8k8.row.col.f32.tf32.tf32.f32 "
        "{%0,%1,%2,%3},{%4,%5,%6,%7},{%8,%9},{%0,%1,%2,%3};"
        : "+f"(c[0]), "+f"(c[1]), "+f"(c[2]), "+f"(c[3])
        : "r"(a[0]), "r"(a[1]), "r"(a[2]), "r"(a[3]), "r"(b[0]), "r"(b[1]));
}

#define LDSV2(lo, hi, addr) \
    asm volatile("ld.shared.v2.u32 {%0,%1}, [%2];" : "=r"(lo), "=r"(hi) : "r"(addr))

__device__ __forceinline__ float fsig(float x) {
    return 1.f / (1.f + __expf(-x));
}
__device__ __forceinline__ float ftanh(float x) {
    return 1.f - 2.f / (__expf(2.f * x) + 1.f);
}

// ===========================================================================
// GI GEMM: g_gi/g_gip with biases folded. acc2 fused into epilogue (reg fix).
// ===========================================================================
__global__ void __launch_bounds__(256) gi_gemm_k(
    const float* __restrict__ x,
    const float* __restrict__ wih,  const float* __restrict__ wihp,
    const float* __restrict__ pah,  const float* __restrict__ masks,
    const float* __restrict__ bih,  const float* __restrict__ bihp,
    const float* __restrict__ bhh,  const float* __restrict__ bhhp)
{
    constexpr int BM = 128, BN = 128, BK = 16, SA = 20;
    constexpr int WRM = 2;
    constexpr int MT = 4, NT = 4, AV = 2, BV = 2;

    __shared__ unsigned sA[2][BM * SA];
    __shared__ unsigned sB[2][BN * SA];

    const int m0 = blockIdx.y * BM;
    const int n0 = blockIdx.x * BN;
    const float* Bg = wih + (size_t)n0 * 520;

    const int tid = threadIdx.x, lane = tid & 31, warp = tid >> 5;
    const int wm = warp % WRM, wn = warp / WRM;

    float acc[MT][NT][4];
#pragma unroll
    for (int i = 0; i < MT; i++)
#pragma unroll
        for (int j = 0; j < NT; j++)
#pragma unroll
            for (int q = 0; q < 4; q++) acc[i][j][q] = 0.f;

    unsigned ra[AV][4], rb[BV][4];

    auto GL = [&](int kc) {
#pragma unroll
        for (int i = 0; i < AV; i++) {
            int s = tid + i * 256; int r = s >> 2; int c = (s & 3) << 2;
            float4 v = *reinterpret_cast<const float4*>(x + (size_t)(m0 + r) * EE + kc * BK + c);
            ra[i][0] = f2tf(v.x); ra[i][1] = f2tf(v.y); ra[i][2] = f2tf(v.z); ra[i][3] = f2tf(v.w);
        }
#pragma unroll
        for (int i = 0; i < BV; i++) {
            int s = tid + i * 256; int r = s >> 2; int c = (s & 3) << 2;
            float4 v = *reinterpret_cast<const float4*>(Bg + (size_t)r * 520 + kc * BK + c);
            rb[i][0] = f2tf(v.x); rb[i][1] = f2tf(v.y); rb[i][2] = f2tf(v.z); rb[i][3] = f2tf(v.w);
        }
    };
    auto SS = [&](int buf) {
#pragma unroll
        for (int i = 0; i < AV; i++) {
            int s = tid + i * 256; int r = s >> 2; int c = (s & 3) << 2;
            *reinterpret_cast<uint4*>(&sA[buf][r * SA + c]) = *reinterpret_cast<uint4*>(ra[i]);
        }
#pragma unroll
        for (int i = 0; i < BV; i++) {
            int s = tid + i * 256; int r = s >> 2; int c = (s & 3) << 2;
            *reinterpret_cast<uint4*>(&sB[buf][r * SA + c]) = *reinterpret_cast<uint4*>(rb[i]);
        }
    };
    auto COMP = [&](int buf) {
#pragma unroll
        for (int k8 = 0; k8 < BK / 8; k8++) {
            unsigned af[MT][4]; unsigned bf[NT][2];
#pragma unroll
            for (int mt = 0; mt < MT; mt++) {
                int r = wm * MT * 16 + mt * 16 + (lane >> 2);
                int c = k8 * 8 + (lane & 3);
                af[mt][0] = sA[buf][r * SA + c];
                af[mt][1] = sA[buf][(r + 8) * SA + c];
                af[mt][2] = sA[buf][r * SA + c + 4];
                af[mt][3] = sA[buf][(r + 8) * SA + c + 4];
            }
#pragma unroll
            for (int nt = 0; nt < NT; nt++) {
                int n = wn * NT * 8 + nt * 8 + (lane >> 2);
                int kk = k8 * 8 + (lane & 3);
                bf[nt][0] = sB[buf][n * SA + kk];
                bf[nt][1] = sB[buf][n * SA + kk + 4];
            }
#pragma unroll
            for (int mt = 0; mt < MT; mt++)
#pragma unroll
                for (int nt = 0; nt < NT; nt++)
                    mma8(acc[mt][nt], af[mt], bf[nt]);
        }
    };

    GL(0); SS(0); __syncthreads();
    constexpr int NKC = EE / BK;
    for (int kc = 0; kc < NKC; kc++) {
        if (kc + 1 < NKC) GL(kc + 1);
        COMP(kc & 1);
        if (kc + 1 < NKC) SS((kc + 1) & 1);
        __syncthreads();
    }

    // Tail: masked prev-action (K=8) fragments
    {
        int s = tid;
        if (s < BM * 2) {
            int r = s >> 1; int c = (s & 1) << 2;
            float4 v = *reinterpret_cast<const float4*>(pah + (size_t)(m0 + r) * AD + c);
            float mk = masks[m0 + r];
            uint4 t4 = { f2tf(v.x * mk), f2tf(v.y * mk), f2tf(v.z * mk), f2tf(v.w * mk) };
            *reinterpret_cast<uint4*>(&sA[0][r * SA + c]) = t4;
        }
        if (s < BN * 2) {
            int n = s >> 1; int c = (s & 1) << 2;
            float4 v = *reinterpret_cast<const float4*>(wih + (size_t)(n0 + n) * 520 + 512 + c);
            uint4 t4 = { f2tf(v.x), f2tf(v.y), f2tf(v.z), f2tf(v.w) };
            *reinterpret_cast<uint4*>(&sB[0][n * SA + c]) = t4;
            float4 w = *reinterpret_cast<const float4*>(wihp + (size_t)(n0 + n) * AD + c);
            uint4 t5 = { f2tf(w.x), f2tf(w.y), f2tf(w.z), f2tf(w.w) };
            *reinterpret_cast<uint4*>(&sB[1][n * SA + c]) = t5;
        }
    }
    __syncthreads();
    {
        unsigned af2[MT][4], b0f[NT][2], b1f[NT][2];
#pragma unroll
        for (int mt = 0; mt < MT; mt++) {
            int r = wm * MT * 16 + mt * 16 + (lane >> 2);
            int c = (lane & 3);
            af2[mt][0] = sA[0][r * SA + c];
            af2[mt][1] = sA[0][(r + 8) * SA + c];
            af2[mt][2] = sA[0][r * SA + c + 4];
            af2[mt][3] = sA[0][(r + 8) * SA + c + 4];
        }
#pragma unroll
        for (int nt = 0; nt < NT; nt++) {
            int n = wn * NT * 8 + nt * 8 + (lane >> 2);
            int kk = (lane & 3);
            b0f[nt][0] = sB[0][n * SA + kk]; b0f[nt][1] = sB[0][n * SA + kk + 4];
            b1f[nt][0] = sB[1][n * SA + kk]; b1f[nt][1] = sB[1][n * SA + kk + 4];
        }

        // Fused tail + epilogue: acc2 is a 4-reg local per tile (no 128-reg array)
#pragma unroll
        for (int mt = 0; mt < MT; mt++)
#pragma unroll
            for (int nt = 0; nt < NT; nt++) {
                mma8(acc[mt][nt], af2[mt], b0f[nt]);
                float acc2l[4] = {0.f, 0.f, 0.f, 0.f};
                mma8(acc2l, af2[mt], b1f[nt]);

                int r = m0 + wm * MT * 16 + mt * 16 + (lane >> 2);
                int c = n0 + wn * NT * 8 + nt * 8 + ((lane & 3) << 1);
                float hb0 = (c < 1024) ? bhh[c] : 0.f;
                float hb1 = (c < 1024) ? bhh[c + 1] : 0.f;
                float b0 = bih[c] + hb0, b1 = bih[c + 1] + hb1;
                *reinterpret_cast<float2*>(&g_gi[(size_t)r * H3 + c]) =
                    make_float2(acc[mt][nt][0] + b0, acc[mt][nt][1] + b1);
                *reinterpret_cast<float2*>(&g_gi[(size_t)(r + 8) * H3 + c]) =
                    make_float2(acc[mt][nt][2] + b0, acc[mt][nt][3] + b1);
                float pb0 = (c < 1024) ? bhhp[c] : 0.f;
                float pb1 = (c < 1024) ? bhhp[c + 1] : 0.f;
                float p0 = bihp[c] + pb0, p1 = bihp[c + 1] + pb1;
                *reinterpret_cast<float2*>(&g_gip[(size_t)r * H3 + c]) =
                    make_float2(acc2l[0] + p0, acc2l[1] + p1);
                *reinterpret_cast<float2*>(&g_gip[(size_t)(r + 8) * H3 + c]) =
                    make_float2(acc2l[2] + p0, acc2l[3] + p1);
            }
    }
}

// ===========================================================================
// Persistent scan. 128 CTAs x 256 threads. k-permuted W and A storage so
// every (k, k+4) fragment pair is one ld.shared.v2.u32 — in-loop LDS halves.
// Permutation within each 8-col block: natural e -> 2(e&3) + (e>>2).
// ===========================================================================
#define SW_LD 520   // == 8 (mod 32): conflict-free LDS.64 for bf
#define SA_LD 40    // == 8 (mod 32): conflict-free LDS.64 for af
#define SMEM_SCAN ((96*SW_LD + 3*64*SA_LD) * 4)

__global__ void __launch_bounds__(256, 1) scan_k(
    const float* __restrict__ whh, const float* __restrict__ whhp,
    const float* __restrict__ masks, const float* __restrict__ ginit,
    const float* __restrict__ bhh, const float* __restrict__ bhhp,
    const float* __restrict__ hxs, const float* __restrict__ hys,
    float* __restrict__ out)
{
    extern __shared__ unsigned sh[];
    unsigned* sW = sh;                      // 96 x 520 (weights, tf32, k-permuted)
    unsigned* sA = sh + 96 * SW_LD;         // 3 stages x 64 x 40 (A chunks, k-permuted)

    const int bx = blockIdx.x;
    const int p  = bx & 15;                 // j-slice index
    const int j0 = p * 32;
    const int m0 = ((bx >> 4) & 3) * 64;
    const int cell = bx >> 6;
    const int grp = bx >> 4;                // (m,cell) group of 16 CTAs

    const float* W  = cell ? whhp : whh;
    const float* gi = cell ? g_gip : g_gi;
    const float* bh = cell ? bhhp : bhh;
    float* outs = out + (cell ? (TNH + NH) : 0);
    float* hf   = out + (cell ? (2 * TNH + NH) : TNH);
    unsigned* bcnt = &g_bars[grp].cnt;
    unsigned* bgen = &g_bars[grp].gen;

    const int tid = threadIdx.x, lane = tid & 31, warp = tid >> 5;
    const int wm = warp & 1;      // row half (32 rows)
    const int wn = warp >> 1;     // col quarter (8 j-cols x 3 gates)

    // ---- preload weights into SMEM (tf32, k-permuted within 8-blocks) ----
    for (int i = tid; i < 96 * 128; i += 256) {
        int rr = i >> 7, cc = (i & 127) << 2;    // natural cols cc..cc+3
        int g = rr >> 5, jj = rr & 31;
        float4 v = *reinterpret_cast<const float4*>(W + (size_t)(g * HH + j0 + jj) * HH + cc);
        unsigned* drow = &sW[rr * SW_LD + (cc & ~7)];
        int odd = (cc & 7) ? 1 : 0;              // cc&7 is 0 or 4
        drow[odd + 0] = f2tf(v.x);
        drow[odd + 2] = f2tf(v.y);
        drow[odd + 4] = f2tf(v.z);
        drow[odd + 6] = f2tf(v.w);
    }

    // ---- init own slice of A(0): global + stage0 SMEM (both permuted) ----
    {
        const float* hsrc = cell ? hys : hxs;
        for (int idx = tid; idx < 64 * 32; idx += 256) {
            int row = idx >> 5, col = idx & 31;
            int n = m0 + row, c = j0 + col;
            float mk = masks[n];
            float v = hsrc[(size_t)n * HH + c] * mk;
            if (cell) v += ginit[(size_t)n * HH + c] * (1.f - mk);
            int e = col & 7;
            int pcol = (col & ~7) + ((e < 4) ? (e << 1) : (((e - 4) << 1) | 1));
            g_A[cell][0][(size_t)n * HH + j0 + pcol] = v;
            sA[row * SA_LD + pcol] = __float_as_uint(v);
        }
    }

    const int cb = j0 + wn * 8 + ((lane & 3) << 1);
    const float2 bn2 = *reinterpret_cast<const float2*>(bh + 2 * HH + cb);
    // permuted position of the (cb, cb+1) pair within its 8-block: (p0, p0+2)
    const int p0 = ((lane & 1) << 2) | ((lane >> 1) & 1);
    const int cpb = j0 + wn * 8 + p0;        // global permuted col of a0 (a1 at +2)
    const int lpb = wn * 8 + p0;             // local (stage) permuted col

    unsigned sA_u32, sW_u32;
    asm("{ .reg .u64 t; cvta.to.shared.u64 t, %1; cvt.u32.u64 %0, t; }"
        : "=r"(sA_u32) : "l"(sA));
    asm("{ .reg .u64 t; cvta.to.shared.u64 t, %1; cvt.u32.u64 %0, t; }"
        : "=r"(sW_u32) : "l"(sW));

    // ---- init barrier (publish A(0) slices) ----
    {
        __syncthreads();
        if (tid == 0) {
            __threadfence();
            unsigned g0;
            asm volatile("ld.acquire.gpu.u32 %0, [%1];" : "=r"(g0) : "l"(bgen));
            unsigned v = atomicAdd(bcnt, 1u);
            if (v == GSIZE - 1) {
                *bcnt = 0u;
                asm volatile("st.release.gpu.u32 [%0], %1;" :: "l"(bgen), "r"(g0 + 1u));
            } else {
                unsigned cur;
                do { asm volatile("ld.acquire.gpu.u32 %0, [%1];" : "=r"(cur) : "l"(bgen)); }
                while (cur < g0 + 1u);
            }
        }
        __syncthreads();
    }

    // ---- register-carried state hq = A(0) fragment (recomputed from inputs) ----
    float2 hq[4];
    {
        const float* hsrc = cell ? hys : hxs;
#pragma unroll
        for (int q = 0; q < 4; q++) {
            int n = m0 + wm * 32 + (q >> 1) * 16 + (lane >> 2) + (q & 1) * 8;
            float mk = masks[n];
            float2 hv = *reinterpret_cast<const float2*>(hsrc + (size_t)n * HH + cb);
            float a0 = hv.x * mk, a1 = hv.y * mk;
            if (cell) {
                float2 gv = *reinterpret_cast<const float2*>(ginit + (size_t)n * HH + cb);
                a0 += gv.x * (1.f - mk);
                a1 += gv.y * (1.f - mk);
            }
            hq[q] = make_float2(a0, a1);
        }
    }

    // ---- initial operand prefetch: gi(0), masks(1), ginit(1) ----
    float2 pir[4], piz[4], pin[4], pg[4];
    float pmask[4];
#pragma unroll
    for (int q = 0; q < 4; q++) {
        int n = m0 + wm * 32 + (q >> 1) * 16 + (lane >> 2) + (q & 1) * 8;
        size_t gb = (size_t)n * H3 + cb;
        pmask[q] = masks[NB + n];
        pir[q] = *reinterpret_cast<const float2*>(gi + gb);
        piz[q] = *reinterpret_cast<const float2*>(gi + gb + HH);
        pin[q] = *reinterpret_cast<const float2*>(gi + gb + 2 * HH);
        pg[q] = cell ? *reinterpret_cast<const float2*>(ginit + (size_t)(NB + n) * HH + cb)
                     : make_float2(0.f, 0.f);
    }

    for (int t = 0; t < TT; t++) {
        const int rb = t & 1;
        const float* Ard = g_A[cell][rb];
        float*       Awr = g_A[cell][rb ^ 1];
        const size_t trow = (size_t)t * NB;
        const float* As = Ard + (size_t)m0 * HH;

        auto issue = [&](int chunk, int stg) {
#pragma unroll
            for (int pp = 0; pp < 2; pp++) {
                int s = tid + pp * 256;
                int row = s >> 3;
                int c4 = (s & 7) << 2;
                unsigned d = sA_u32 + ((((stg * 64) + row) * SA_LD + c4) << 2);
                const float* src = As + (size_t)row * HH + chunk * 32 + c4;
                asm volatile("cp.async.cg.shared.global [%0], [%1], 16;" :: "r"(d), "l"(src));
            }
        };

        // chunk p already in stage 0 (STS from previous epilogue / init)
        issue((p + 1) & 15, 1); asm volatile("cp.async.commit_group;");
        issue((p + 2) & 15, 2); asm volatile("cp.async.commit_group;");

        float acc[3][2][4];
#pragma unroll
        for (int g = 0; g < 3; g++)
#pragma unroll
            for (int mt = 0; mt < 2; mt++)
#pragma unroll
                for (int q = 0; q < 4; q++) acc[g][mt][q] = 0.f;

        int sr = 0;
        for (int i = 0; i < 16; i++) {
            const int chunk = (p + i) & 15;
            if (i > 0) {
                if (i < 15) asm volatile("cp.async.wait_group 1;");
                else        asm volatile("cp.async.wait_group 0;");
                __syncthreads();
                if (i <= 13) {
                    int sw = sr + 2; if (sw >= 3) sw -= 3;
                    issue((p + i + 2) & 15, sw);
                    asm volatile("cp.async.commit_group;");
                }
            }
            const unsigned stg_u32 = sA_u32 + ((sr * 64 * SA_LD) << 2);
#pragma unroll
            for (int k8 = 0; k8 < 4; k8++) {
                const int ck2 = k8 * 8 + ((lane & 3) << 1);   // permuted word offset in row
                unsigned af[2][4];
#pragma unroll
                for (int mt = 0; mt < 2; mt++) {
                    int r = wm * 32 + mt * 16 + (lane >> 2);
                    unsigned a0 = stg_u32 + ((r * SA_LD + ck2) << 2);
                    LDSV2(af[mt][0], af[mt][2], a0);
                    LDSV2(af[mt][1], af[mt][3], a0 + ((8 * SA_LD) << 2));
                }
                const int kgw = chunk * 32 + ck2;
#pragma unroll
                for (int g = 0; g < 3; g++) {
                    int bn = g * 32 + wn * 8 + (lane >> 2);
                    unsigned bf[2];
                    LDSV2(bf[0], bf[1], sW_u32 + ((bn * SW_LD + kgw) << 2));
#pragma unroll
                    for (int mt = 0; mt < 2; mt++)
                        mma8(acc[g][mt], af[mt], bf);
                }
            }
            sr++; if (sr >= 3) sr -= 3;
        }

        if (t < TT - 1) {
            __syncthreads();   // stage0 about to be overwritten by STS below

            // ---- gate math; h parked in acc[0], next-A stored (permuted) + STS'd ----
#pragma unroll
            for (int mt = 0; mt < 2; mt++)
#pragma unroll
                for (int half = 0; half < 2; half++) {
                    int q = mt * 2 + half;
                    int rowl = wm * 32 + mt * 16 + (lane >> 2) + half * 8;
                    int n = m0 + rowl;
                    float mnx = pmask[q];
                    float rr0 = fsig(pir[q].x + acc[0][mt][half * 2]);
                    float rr1 = fsig(pir[q].y + acc[0][mt][half * 2 + 1]);
                    float zz0 = fsig(piz[q].x + acc[1][mt][half * 2]);
                    float zz1 = fsig(piz[q].y + acc[1][mt][half * 2 + 1]);
                    float nn0 = ftanh(pin[q].x + rr0 * (acc[2][mt][half * 2] + bn2.x));
                    float nn1 = ftanh(pin[q].y + rr1 * (acc[2][mt][half * 2 + 1] + bn2.y));
                    float h0 = (1.f - zz0) * nn0 + zz0 * hq[q].x;
                    float h1 = (1.f - zz1) * nn1 + zz1 * hq[q].y;
                    acc[0][mt][half * 2]     = h0;
                    acc[0][mt][half * 2 + 1] = h1;
                    float a0 = h0 * mnx + pg[q].x * (1.f - mnx);
                    float a1 = h1 * mnx + pg[q].y * (1.f - mnx);
                    Awr[(size_t)n * HH + cpb]     = a0;
                    Awr[(size_t)n * HH + cpb + 2] = a1;
                    hq[q] = make_float2(a0, a1);
                    unsigned ad = sA_u32 + ((rowl * SA_LD + lpb) << 2);
                    asm volatile("st.shared.u32 [%0], %1;" :: "r"(ad), "f"(a0));
                    asm volatile("st.shared.u32 [%0], %1;" :: "r"(ad + 8), "f"(a1));
                }

            // ---- arrive (non-blocking) ----
            __syncthreads();
            unsigned tgt = 0u;
            if (tid == 0) {
                __threadfence();
                unsigned g0;
                asm volatile("ld.acquire.gpu.u32 %0, [%1];" : "=r"(g0) : "l"(bgen));
                tgt = g0 + 1u;
                unsigned v = atomicAdd(bcnt, 1u);
                if (v == GSIZE - 1) {
                    *bcnt = 0u;
                    asm volatile("st.release.gpu.u32 [%0], %1;" :: "l"(bgen), "r"(tgt));
                }
            }

            // ---- shadow work: outs stores + next-step prefetch ----
#pragma unroll
            for (int mt = 0; mt < 2; mt++)
#pragma unroll
                for (int half = 0; half < 2; half++) {
                    int n = m0 + wm * 32 + mt * 16 + (lane >> 2) + half * 8;
                    *reinterpret_cast<float2*>(outs + (trow + n) * HH + cb) =
                        make_float2(acc[0][mt][half * 2], acc[0][mt][half * 2 + 1]);
                }
            const size_t trow1 = trow + NB;
            const bool hasnext2 = (t + 2 < TT);
#pragma unroll
            for (int q = 0; q < 4; q++) {
                int n = m0 + wm * 32 + (q >> 1) * 16 + (lane >> 2) + (q & 1) * 8;
                size_t gb = (trow1 + n) * (size_t)H3 + cb;
                pmask[q] = hasnext2 ? masks[trow1 + NB + n] : 0.f;
                pir[q] = *reinterpret_cast<const float2*>(gi + gb);
                piz[q] = *reinterpret_cast<const float2*>(gi + gb + HH);
                pin[q] = *reinterpret_cast<const float2*>(gi + gb + 2 * HH);
                pg[q] = (cell && hasnext2)
                    ? *reinterpret_cast<const float2*>(
                          ginit + (size_t)(trow1 + NB + n) * HH + cb)
                    : make_float2(0.f, 0.f);
            }

            // ---- wait ----
            if (tid == 0) {
                unsigned cur;
                do { asm volatile("ld.acquire.gpu.u32 %0, [%1];" : "=r"(cur) : "l"(bgen)); }
                while (cur < tgt);
            }
            __syncthreads();
        } else {
            // ---- final step: outs + final hidden state ----
#pragma unroll
            for (int mt = 0; mt < 2; mt++)
#pragma unroll
                for (int half = 0; half < 2; half++) {
                    int q = mt * 2 + half;
                    int n = m0 + wm * 32 + mt * 16 + (lane >> 2) + half * 8;
                    size_t mrow = trow + n;
                    float rr0 = fsig(pir[q].x + acc[0][mt][half * 2]);
                    float rr1 = fsig(pir[q].y + acc[0][mt][half * 2 + 1]);
                    float zz0 = fsig(piz[q].x + acc[1][mt][half * 2]);
                    float zz1 = fsig(piz[q].y + acc[1][mt][half * 2 + 1]);
                    float nn0 = ftanh(pin[q].x + rr0 * (acc[2][mt][half * 2] + bn2.x));
                    float nn1 = ftanh(pin[q].y + rr1 * (acc[2][mt][half * 2 + 1] + bn2.y));
                    float h0 = (1.f - zz0) * nn0 + zz0 * hq[q].x;
                    float h1 = (1.f - zz1) * nn1 + zz1 * hq[q].y;
                    *reinterpret_cast<float2*>(outs + mrow * HH + cb) = make_float2(h0, h1);
                    *reinterpret_cast<float2*>(hf + (size_t)n * HH + cb) = make_float2(h0, h1);
                }
        }
    }
}

extern "C" void kernel_launch(void* const* d_in, const int* in_sizes, int n_in,
                              void* d_out, int out_size)
{
    const float* x     = (const float*)d_in[0];
    const float* hxs   = (const float*)d_in[1];
    const float* hys   = (const float*)d_in[2];
    const float* ginit = (const float*)d_in[3];
    const float* masks = (const float*)d_in[4];
    const float* pah   = (const float*)d_in[5];
    const float* wih   = (const float*)d_in[6];
    const float* whh   = (const float*)d_in[7];
    const float* bih   = (const float*)d_in[8];
    const float* bhh   = (const float*)d_in[9];
    const float* wihp  = (const float*)d_in[10];
    const float* whhp  = (const float*)d_in[11];
    const float* bihp  = (const float*)d_in[12];
    const float* bhhp  = (const float*)d_in[13];
    float* out = (float*)d_out;

    gi_gemm_k<<<dim3(12, 256), 256>>>(x, wih, wihp, pah, masks, bih, bihp, bhh, bhhp);

    cudaFuncSetAttribute(scan_k, cudaFuncAttributeMaxDynamicSharedMemorySize, SMEM_SCAN);
    scan_k<<<NCTA, 256, SMEM_SCAN>>>(whh, whhp, masks, ginit, bhh, bhhp, hxs, hys, out);
}

// round 10
// speedup vs baseline: 1.0850x; 1.0850x over previous
#include <cuda_runtime.h>
#include <math.h>

#define TT 128
#define NB 256
#define EE 512
#define AD 8
#define HH 512
#define H3 1536
#define TN (TT*NB)
#define TNH ((size_t)TN*HH)
#define NH (NB*HH)
#define NCTA 128
#define NGROUP 8
#define GSIZE 16

// Scratch (no cudaMalloc allowed)
__device__ float g_gi [(size_t)TN * H3];   // input-side gates, cell 1 (+ b_ih + b_hh[r,z])
__device__ float g_gip[(size_t)TN * H3];   // input-side gates, cell 2
__device__ float g_A [2][2][NH];           // masked hidden state, parity double-buffer
struct __align__(128) Bar { unsigned cnt; unsigned gen; unsigned pad[30]; };
__device__ Bar g_bars[NGROUP];

__device__ __forceinline__ unsigned f2tf(float x) {
    unsigned r;
    asm("cvt.rna.tf32.f32 %0, %1;" : "=r"(r) : "f"(x));
    return r;
}

__device__ __forceinline__ void mma8(float* c, const unsigned* a, const unsigned* b) {
    asm volatile(
        "mma.sync.aligned.m16n8k8.row.col.f32.tf32.tf32.f32 "
        "{%0,%1,%2,%3},{%4,%5,%6,%7},{%8,%9},{%0,%1,%2,%3};"
        : "+f"(c[0]), "+f"(c[1]), "+f"(c[2]), "+f"(c[3])
        : "r"(a[0]), "r"(a[1]), "r"(a[2]), "r"(a[3]), "r"(b[0]), "r"(b[1]));
}

__device__ __forceinline__ float fsig(float x) {
    return 1.f / (1.f + __expf(-x));
}
__device__ __forceinline__ float ftanh(float x) {
    return 1.f - 2.f / (__expf(2.f * x) + 1.f);
}

// ===========================================================================
// GI GEMM (R8 version, known good): g_gi/g_gip with biases folded
// ===========================================================================
__global__ void __launch_bounds__(256) gi_gemm_k(
    const float* __restrict__ x,
    const float* __restrict__ wih,  const float* __restrict__ wihp,
    const float* __restrict__ pah,  const float* __restrict__ masks,
    const float* __restrict__ bih,  const float* __restrict__ bihp,
    const float* __restrict__ bhh,  const float* __restrict__ bhhp)
{
    constexpr int BM = 128, BN = 128, BK = 16, SA = 20;
    constexpr int WRM = 2;
    constexpr int MT = 4, NT = 4, AV = 2, BV = 2;

    __shared__ unsigned sA[2][BM * SA];
    __shared__ unsigned sB[2][BN * SA];

    const int m0 = blockIdx.y * BM;
    const int n0 = blockIdx.x * BN;
    const float* Bg = wih + (size_t)n0 * 520;

    const int tid = threadIdx.x, lane = tid & 31, warp = tid >> 5;
    const int wm = warp % WRM, wn = warp / WRM;

    float acc[MT][NT][4];
    float acc2[MT][NT][4];
#pragma unroll
    for (int i = 0; i < MT; i++)
#pragma unroll
        for (int j = 0; j < NT; j++)
#pragma unroll
            for (int q = 0; q < 4; q++) { acc[i][j][q] = 0.f; acc2[i][j][q] = 0.f; }

    unsigned ra[AV][4], rb[BV][4];

    auto GL = [&](int kc) {
#pragma unroll
        for (int i = 0; i < AV; i++) {
            int s = tid + i * 256; int r = s >> 2; int c = (s & 3) << 2;
            float4 v = *reinterpret_cast<const float4*>(x + (size_t)(m0 + r) * EE + kc * BK + c);
            ra[i][0] = f2tf(v.x); ra[i][1] = f2tf(v.y); ra[i][2] = f2tf(v.z); ra[i][3] = f2tf(v.w);
        }
#pragma unroll
        for (int i = 0; i < BV; i++) {
            int s = tid + i * 256; int r = s >> 2; int c = (s & 3) << 2;
            float4 v = *reinterpret_cast<const float4*>(Bg + (size_t)r * 520 + kc * BK + c);
            rb[i][0] = f2tf(v.x); rb[i][1] = f2tf(v.y); rb[i][2] = f2tf(v.z); rb[i][3] = f2tf(v.w);
        }
    };
    auto SS = [&](int buf) {
#pragma unroll
        for (int i = 0; i < AV; i++) {
            int s = tid + i * 256; int r = s >> 2; int c = (s & 3) << 2;
            *reinterpret_cast<uint4*>(&sA[buf][r * SA + c]) = *reinterpret_cast<uint4*>(ra[i]);
        }
#pragma unroll
        for (int i = 0; i < BV; i++) {
            int s = tid + i * 256; int r = s >> 2; int c = (s & 3) << 2;
            *reinterpret_cast<uint4*>(&sB[buf][r * SA + c]) = *reinterpret_cast<uint4*>(rb[i]);
        }
    };
    auto COMP = [&](int buf) {
#pragma unroll
        for (int k8 = 0; k8 < BK / 8; k8++) {
            unsigned af[MT][4]; unsigned bf[NT][2];
#pragma unroll
            for (int mt = 0; mt < MT; mt++) {
                int r = wm * MT * 16 + mt * 16 + (lane >> 2);
                int c = k8 * 8 + (lane & 3);
                af[mt][0] = sA[buf][r * SA + c];
                af[mt][1] = sA[buf][(r + 8) * SA + c];
                af[mt][2] = sA[buf][r * SA + c + 4];
                af[mt][3] = sA[buf][(r + 8) * SA + c + 4];
            }
#pragma unroll
            for (int nt = 0; nt < NT; nt++) {
                int n = wn * NT * 8 + nt * 8 + (lane >> 2);
                int kk = k8 * 8 + (lane & 3);
                bf[nt][0] = sB[buf][n * SA + kk];
                bf[nt][1] = sB[buf][n * SA + kk + 4];
            }
#pragma unroll
            for (int mt = 0; mt < MT; mt++)
#pragma unroll
                for (int nt = 0; nt < NT; nt++)
                    mma8(acc[mt][nt], af[mt], bf[nt]);
        }
    };

    GL(0); SS(0); __syncthreads();
    constexpr int NKC = EE / BK;
    for (int kc = 0; kc < NKC; kc++) {
        if (kc + 1 < NKC) GL(kc + 1);
        COMP(kc & 1);
        if (kc + 1 < NKC) SS((kc + 1) & 1);
        __syncthreads();
    }

    // Tail: masked prev-action (K=8)
    {
        int s = tid;
        if (s < BM * 2) {
            int r = s >> 1; int c = (s & 1) << 2;
            float4 v = *reinterpret_cast<const float4*>(pah + (size_t)(m0 + r) * AD + c);
            float mk = masks[m0 + r];
            uint4 t4 = { f2tf(v.x * mk), f2tf(v.y * mk), f2tf(v.z * mk), f2tf(v.w * mk) };
            *reinterpret_cast<uint4*>(&sA[0][r * SA + c]) = t4;
        }
        if (s < BN * 2) {
            int n = s >> 1; int c = (s & 1) << 2;
            float4 v = *reinterpret_cast<const float4*>(wih + (size_t)(n0 + n) * 520 + 512 + c);
            uint4 t4 = { f2tf(v.x), f2tf(v.y), f2tf(v.z), f2tf(v.w) };
            *reinterpret_cast<uint4*>(&sB[0][n * SA + c]) = t4;
            float4 w = *reinterpret_cast<const float4*>(wihp + (size_t)(n0 + n) * AD + c);
            uint4 t5 = { f2tf(w.x), f2tf(w.y), f2tf(w.z), f2tf(w.w) };
            *reinterpret_cast<uint4*>(&sB[1][n * SA + c]) = t5;
        }
    }
    __syncthreads();
    {
        unsigned af2[MT][4], b0f[NT][2], b1f[NT][2];
#pragma unroll
        for (int mt = 0; mt < MT; mt++) {
            int r = wm * MT * 16 + mt * 16 + (lane >> 2);
            int c = (lane & 3);
            af2[mt][0] = sA[0][r * SA + c];
            af2[mt][1] = sA[0][(r + 8) * SA + c];
            af2[mt][2] = sA[0][r * SA + c + 4];
            af2[mt][3] = sA[0][(r + 8) * SA + c + 4];
        }
#pragma unroll
        for (int nt = 0; nt < NT; nt++) {
            int n = wn * NT * 8 + nt * 8 + (lane >> 2);
            int kk = (lane & 3);
            b0f[nt][0] = sB[0][n * SA + kk]; b0f[nt][1] = sB[0][n * SA + kk + 4];
            b1f[nt][0] = sB[1][n * SA + kk]; b1f[nt][1] = sB[1][n * SA + kk + 4];
        }
#pragma unroll
        for (int mt = 0; mt < MT; mt++)
#pragma unroll
            for (int nt = 0; nt < NT; nt++) {
                mma8(acc[mt][nt], af2[mt], b0f[nt]);
                mma8(acc2[mt][nt], af2[mt], b1f[nt]);
            }
    }

#pragma unroll
    for (int mt = 0; mt < MT; mt++)
#pragma unroll
        for (int nt = 0; nt < NT; nt++) {
            int r = m0 + wm * MT * 16 + mt * 16 + (lane >> 2);
            int c = n0 + wn * NT * 8 + nt * 8 + ((lane & 3) << 1);
            float hb0 = (c < 1024) ? bhh[c] : 0.f;
            float hb1 = (c < 1024) ? bhh[c + 1] : 0.f;
            float b0 = bih[c] + hb0, b1 = bih[c + 1] + hb1;
            *reinterpret_cast<float2*>(&g_gi[(size_t)r * H3 + c]) =
                make_float2(acc[mt][nt][0] + b0, acc[mt][nt][1] + b1);
            *reinterpret_cast<float2*>(&g_gi[(size_t)(r + 8) * H3 + c]) =
                make_float2(acc[mt][nt][2] + b0, acc[mt][nt][3] + b1);
            float pb0 = (c < 1024) ? bhhp[c] : 0.f;
            float pb1 = (c < 1024) ? bhhp[c + 1] : 0.f;
            float p0 = bihp[c] + pb0, p1 = bihp[c + 1] + pb1;
            *reinterpret_cast<float2*>(&g_gip[(size_t)r * H3 + c]) =
                make_float2(acc2[mt][nt][0] + p0, acc2[mt][nt][1] + p1);
            *reinterpret_cast<float2*>(&g_gip[(size_t)(r + 8) * H3 + c]) =
                make_float2(acc2[mt][nt][2] + p0, acc2[mt][nt][3] + p1);
        }
}

// ===========================================================================
// Persistent scan. 128 CTAs x 512 threads (4 warps/SMSP). Warp grid 4x4:
// (row quarter, 16 rows) x (col quarter: 8 j-cols, all 3 gates). Each thread
// holds r/z/n for its own elements -> fused epilogue, no exchange.
// Group barrier + shadow prefetch, own-slice STS, register h (R8 skeleton).
// ===========================================================================
#define SW_LD 516
#define SA_LD 36
#define SMEM_SCAN ((96*SW_LD + 3*64*SA_LD) * 4)

__global__ void __launch_bounds__(512, 1) scan_k(
    const float* __restrict__ whh, const float* __restrict__ whhp,
    const float* __restrict__ masks, const float* __restrict__ ginit,
    const float* __restrict__ bhh, const float* __restrict__ bhhp,
    const float* __restrict__ hxs, const float* __restrict__ hys,
    float* __restrict__ out)
{
    extern __shared__ unsigned sh[];
    unsigned* sW = sh;                      // 96 x 516 (weights, tf32)
    unsigned* sA = sh + 96 * SW_LD;         // 3 stages x 64 x 36 (A chunks)

    const int bx = blockIdx.x;
    const int p  = bx & 15;                 // j-slice index
    const int j0 = p * 32;
    const int m0 = ((bx >> 4) & 3) * 64;
    const int cell = bx >> 6;
    const int grp = bx >> 4;                // (m,cell) group of 16 CTAs

    const float* W  = cell ? whhp : whh;
    const float* gi = cell ? g_gip : g_gi;
    const float* bh = cell ? bhhp : bhh;
    float* outs = out + (cell ? (TNH + NH) : 0);
    float* hf   = out + (cell ? (2 * TNH + NH) : TNH);
    unsigned* bcnt = &g_bars[grp].cnt;
    unsigned* bgen = &g_bars[grp].gen;

    const int tid = threadIdx.x, lane = tid & 31, warp = tid >> 5;
    const int wq = warp & 3;      // row quarter (16 rows)
    const int wc = warp >> 2;     // col quarter (8 j-cols, x3 gates)

    // ---- preload weights into SMEM (tf32, RNA) ----
    for (int i = tid; i < 96 * 128; i += 512) {
        int rr = i >> 7, cc = (i & 127) << 2;
        int g = rr >> 5, jj = rr & 31;
        float4 v = *reinterpret_cast<const float4*>(W + (size_t)(g * HH + j0 + jj) * HH + cc);
        unsigned* d = &sW[rr * SW_LD + cc];
        d[0] = f2tf(v.x); d[1] = f2tf(v.y); d[2] = f2tf(v.z); d[3] = f2tf(v.w);
    }

    // ---- init own slice of A(0): global + stage0 SMEM ----
    {
        const float* hsrc = cell ? hys : hxs;
        for (int idx = tid; idx < 64 * 32; idx += 512) {
            int row = idx >> 5, col = idx & 31;
            int n = m0 + row, c = j0 + col;
            float mk = masks[n];
            float v = hsrc[(size_t)n * HH + c] * mk;
            if (cell) v += ginit[(size_t)n * HH + c] * (1.f - mk);
            g_A[cell][0][(size_t)n * HH + c] = v;
            sA[row * SA_LD + col] = __float_as_uint(v);
        }
    }

    const int cb = j0 + wc * 8 + ((lane & 3) << 1);
    const float2 bn2 = *reinterpret_cast<const float2*>(bh + 2 * HH + cb);

    unsigned sA_u32;
    asm("{ .reg .u64 t; cvta.to.shared.u64 t, %1; cvt.u32.u64 %0, t; }"
        : "=r"(sA_u32) : "l"(sA));

    // ---- init barrier (publish A(0) slices) ----
    {
        __syncthreads();
        if (tid == 0) {
            __threadfence();
            unsigned g0;
            asm volatile("ld.acquire.gpu.u32 %0, [%1];" : "=r"(g0) : "l"(bgen));
            unsigned v = atomicAdd(bcnt, 1u);
            if (v == GSIZE - 1) {
                *bcnt = 0u;
                asm volatile("st.release.gpu.u32 [%0], %1;" :: "l"(bgen), "r"(g0 + 1u));
            } else {
                unsigned cur;
                do { asm volatile("ld.acquire.gpu.u32 %0, [%1];" : "=r"(cur) : "l"(bgen)); }
                while (cur < g0 + 1u);
            }
        }
        __syncthreads();
    }

    // ---- register-carried state hq = A(0) fragment (from own stage0) ----
    float2 hq[2];
#pragma unroll
    for (int half = 0; half < 2; half++) {
        int row = wq * 16 + (lane >> 2) + half * 8;
        int col = wc * 8 + ((lane & 3) << 1);
        hq[half] = *reinterpret_cast<const float2*>(
            reinterpret_cast<const float*>(sA) + row * SA_LD + col);
    }

    // ---- initial operand prefetch: gi(0), masks(1), ginit(1) ----
    float2 pir[2], piz[2], pin[2], pg[2];
    float pmask[2];
#pragma unroll
    for (int half = 0; half < 2; half++) {
        int n = m0 + wq * 16 + (lane >> 2) + half * 8;
        size_t gb = (size_t)n * H3 + cb;
        pmask[half] = masks[NB + n];
        pir[half] = *reinterpret_cast<const float2*>(gi + gb);
        piz[half] = *reinterpret_cast<const float2*>(gi + gb + HH);
        pin[half] = *reinterpret_cast<const float2*>(gi + gb + 2 * HH);
        pg[half] = cell ? *reinterpret_cast<const float2*>(ginit + (size_t)(NB + n) * HH + cb)
                        : make_float2(0.f, 0.f);
    }

    for (int t = 0; t < TT; t++) {
        const int rb = t & 1;
        const float* Ard = g_A[cell][rb];
        float*       Awr = g_A[cell][rb ^ 1];
        const size_t trow = (size_t)t * NB;
        const float* As = Ard + (size_t)m0 * HH;

        auto issue = [&](int chunk, int stg) {
            int row = tid >> 3;
            int c4 = (tid & 7) << 2;
            unsigned d = sA_u32 + ((((stg * 64) + row) * SA_LD + c4) << 2);
            const float* src = As + (size_t)row * HH + chunk * 32 + c4;
            asm volatile("cp.async.cg.shared.global [%0], [%1], 16;" :: "r"(d), "l"(src));
        };

        // chunk p already in stage 0 (STS from previous epilogue / init)
        issue((p + 1) & 15, 1); asm volatile("cp.async.commit_group;");
        issue((p + 2) & 15, 2); asm volatile("cp.async.commit_group;");

        float acc[3][4];
#pragma unroll
        for (int g = 0; g < 3; g++)
#pragma unroll
            for (int q = 0; q < 4; q++) acc[g][q] = 0.f;

        int sr = 0;
        for (int i = 0; i < 16; i++) {
            if (i > 0) {
                if (i < 15) asm volatile("cp.async.wait_group 1;");
                else        asm volatile("cp.async.wait_group 0;");
                __syncthreads();
                if (i <= 13) {
                    int sw = sr + 2; if (sw >= 3) sw -= 3;
                    issue((p + i + 2) & 15, sw);
                    asm volatile("cp.async.commit_group;");
                }
            }
            const int chunk = (p + i) & 15;
            const unsigned* sab = sA + sr * 64 * SA_LD;
#pragma unroll
            for (int k8 = 0; k8 < 4; k8++) {
                const int ck = k8 * 8 + (lane & 3);
                unsigned af[4];
                {
                    int r = wq * 16 + (lane >> 2);
                    af[0] = sab[r * SA_LD + ck];
                    af[1] = sab[(r + 8) * SA_LD + ck];
                    af[2] = sab[r * SA_LD + ck + 4];
                    af[3] = sab[(r + 8) * SA_LD + ck + 4];
                }
                const int kg = chunk * 32 + ck;
#pragma unroll
                for (int g = 0; g < 3; g++) {
                    int bn = g * 32 + wc * 8 + (lane >> 2);
                    unsigned bf[2] = { sW[bn * SW_LD + kg], sW[bn * SW_LD + kg + 4] };
                    mma8(acc[g], af, bf);
                }
            }
            sr++; if (sr >= 3) sr -= 3;
        }

        if (t < TT - 1) {
            __syncthreads();   // stage0 about to be overwritten by STS below

            // ---- gate math; h parked in acc[0], next-A stored + STS'd ----
#pragma unroll
            for (int half = 0; half < 2; half++) {
                int rowl = wq * 16 + (lane >> 2) + half * 8;
                int n = m0 + rowl;
                float mnx = pmask[half];
                float rr0 = fsig(pir[half].x + acc[0][half * 2]);
                float rr1 = fsig(pir[half].y + acc[0][half * 2 + 1]);
                float zz0 = fsig(piz[half].x + acc[1][half * 2]);
                float zz1 = fsig(piz[half].y + acc[1][half * 2 + 1]);
                float nn0 = ftanh(pin[half].x + rr0 * (acc[2][half * 2] + bn2.x));
                float nn1 = ftanh(pin[half].y + rr1 * (acc[2][half * 2 + 1] + bn2.y));
                float h0 = (1.f - zz0) * nn0 + zz0 * hq[half].x;
                float h1 = (1.f - zz1) * nn1 + zz1 * hq[half].y;
                acc[0][half * 2]     = h0;
                acc[0][half * 2 + 1] = h1;
                float a0 = h0 * mnx + pg[half].x * (1.f - mnx);
                float a1 = h1 * mnx + pg[half].y * (1.f - mnx);
                *reinterpret_cast<float2*>(Awr + (size_t)n * HH + cb) = make_float2(a0, a1);
                hq[half] = make_float2(a0, a1);
                unsigned ad = sA_u32 +
                    ((rowl * SA_LD + wc * 8 + ((lane & 3) << 1)) << 2);
                asm volatile("st.shared.v2.f32 [%0], {%1,%2};"
                             :: "r"(ad), "f"(a0), "f"(a1));
            }

            // ---- arrive (non-blocking) ----
            __syncthreads();
            unsigned tgt = 0u;
            if (tid == 0) {
                __threadfence();
                unsigned g0;
                asm volatile("ld.acquire.gpu.u32 %0, [%1];" : "=r"(g0) : "l"(bgen));
                tgt = g0 + 1u;
                unsigned v = atomicAdd(bcnt, 1u);
                if (v == GSIZE - 1) {
                    *bcnt = 0u;
                    asm volatile("st.release.gpu.u32 [%0], %1;" :: "l"(bgen), "r"(tgt));
                }
            }

            // ---- shadow work: outs stores + next-step prefetch ----
#pragma unroll
            for (int half = 0; half < 2; half++) {
                int n = m0 + wq * 16 + (lane >> 2) + half * 8;
                *reinterpret_cast<float2*>(outs + (trow + n) * HH + cb) =
                    make_float2(acc[0][half * 2], acc[0][half * 2 + 1]);
            }
            const size_t trow1 = trow + NB;
            const bool hasnext2 = (t + 2 < TT);
#pragma unroll
            for (int half = 0; half < 2; half++) {
                int n = m0 + wq * 16 + (lane >> 2) + half * 8;
                size_t gb = (trow1 + n) * (size_t)H3 + cb;
                pmask[half] = hasnext2 ? masks[trow1 + NB + n] : 0.f;
                pir[half] = *reinterpret_cast<const float2*>(gi + gb);
                piz[half] = *reinterpret_cast<const float2*>(gi + gb + HH);
                pin[half] = *reinterpret_cast<const float2*>(gi + gb + 2 * HH);
                pg[half] = (cell && hasnext2)
                    ? *reinterpret_cast<const float2*>(
                          ginit + (size_t)(trow1 + NB + n) * HH + cb)
                    : make_float2(0.f, 0.f);
            }

            // ---- wait ----
            if (tid == 0) {
                unsigned cur;
                do { asm volatile("ld.acquire.gpu.u32 %0, [%1];" : "=r"(cur) : "l"(bgen)); }
                while (cur < tgt);
            }
            __syncthreads();
        } else {
            // ---- final step: outs + final hidden state ----
#pragma unroll
            for (int half = 0; half < 2; half++) {
                int n = m0 + wq * 16 + (lane >> 2) + half * 8;
                size_t mrow = trow + n;
                float rr0 = fsig(pir[half].x + acc[0][half * 2]);
                float rr1 = fsig(pir[half].y + acc[0][half * 2 + 1]);
                float zz0 = fsig(piz[half].x + acc[1][half * 2]);
                float zz1 = fsig(piz[half].y + acc[1][half * 2 + 1]);
                float nn0 = ftanh(pin[half].x + rr0 * (acc[2][half * 2] + bn2.x));
                float nn1 = ftanh(pin[half].y + rr1 * (acc[2][half * 2 + 1] + bn2.y));
                float h0 = (1.f - zz0) * nn0 + zz0 * hq[half].x;
                float h1 = (1.f - zz1) * nn1 + zz1 * hq[half].y;
                *reinterpret_cast<float2*>(outs + mrow * HH + cb) = make_float2(h0, h1);
                *reinterpret_cast<float2*>(hf + (size_t)n * HH + cb) = make_float2(h0, h1);
            }
        }
    }
}

extern "C" void kernel_launch(void* const* d_in, const int* in_sizes, int n_in,
                              void* d_out, int out_size)
{
    const float* x     = (const float*)d_in[0];
    const float* hxs   = (const float*)d_in[1];
    const float* hys   = (const float*)d_in[2];
    const float* ginit = (const float*)d_in[3];
    const float* masks = (const float*)d_in[4];
    const float* pah   = (const float*)d_in[5];
    const float* wih   = (const float*)d_in[6];
    const float* whh   = (const float*)d_in[7];
    const float* bih   = (const float*)d_in[8];
    const float* bhh   = (const float*)d_in[9];
    const float* wihp  = (const float*)d_in[10];
    const float* whhp  = (const float*)d_in[11];
    const float* bihp  = (const float*)d_in[12];
    const float* bhhp  = (const float*)d_in[13];
    float* out = (float*)d_out;

    gi_gemm_k<<<dim3(12, 256), 256>>>(x, wih, wihp, pah, masks, bih, bihp, bhh, bhhp);

    cudaFuncSetAttribute(scan_k, cudaFuncAttributeMaxDynamicSharedMemorySize, SMEM_SCAN);
    scan_k<<<NCTA, 512, SMEM_SCAN>>>(whh, whhp, masks, ginit, bhh, bhhp, hxs, hys, out);
}

// round 12
// speedup vs baseline: 1.3658x; 1.2588x over previous
#include <cuda_runtime.h>
#include <cuda_fp16.h>
#include <math.h>

#define TT 128
#define NB 256
#define EE 512
#define AD 8
#define HH 512
#define H3 1536
#define TN (TT*NB)
#define TNH ((size_t)TN*HH)
#define NH (NB*HH)
#define NCTA 128
#define NGROUP 8
#define GSIZE 16

// Scratch (no cudaMalloc allowed)
__device__ float g_gi [(size_t)TN * H3];
__device__ float g_gip[(size_t)TN * H3];
__device__ unsigned g_A16[2][2][NH/2];     // masked hidden state as half2 words
struct __align__(128) Bar { unsigned cnt; unsigned gen; unsigned pad[30]; };
__device__ Bar g_bars[NGROUP];

__device__ __forceinline__ unsigned f2tf(float x) {
    unsigned r;
    asm("cvt.rna.tf32.f32 %0, %1;" : "=r"(r) : "f"(x));
    return r;
}

__device__ __forceinline__ unsigned pack_h2(float a, float b) {
    __half2 h = __floats2half2_rn(a, b);
    return *reinterpret_cast<unsigned*>(&h);
}

// tf32 m16n8k8 (gi GEMM)
__device__ __forceinline__ void mma8(float* c, const unsigned* a, const unsigned* b) {
    asm volatile(
        "mma.sync.aligned.m16n8k8.row.col.f32.tf32.tf32.f32 "
        "{%0,%1,%2,%3},{%4,%5,%6,%7},{%8,%9},{%0,%1,%2,%3};"
        : "+f"(c[0]), "+f"(c[1]), "+f"(c[2]), "+f"(c[3])
        : "r"(a[0]), "r"(a[1]), "r"(a[2]), "r"(a[3]), "r"(b[0]), "r"(b[1]));
}

// fp16 m16n8k16, fp32 accumulate (scan GEMM)
__device__ __forceinline__ void mma16h(float* c, const unsigned* a, const unsigned* b) {
    asm volatile(
        "mma.sync.aligned.m16n8k16.row.col.f32.f16.f16.f32 "
        "{%0,%1,%2,%3},{%4,%5,%6,%7},{%8,%9},{%0,%1,%2,%3};"
        : "+f"(c[0]), "+f"(c[1]), "+f"(c[2]), "+f"(c[3])
        : "r"(a[0]), "r"(a[1]), "r"(a[2]), "r"(a[3]), "r"(b[0]), "r"(b[1]));
}

__device__ __forceinline__ float fsig(float x) { return 1.f / (1.f + __expf(-x)); }
__device__ __forceinline__ float ftanh(float x) { return 1.f - 2.f / (__expf(2.f * x) + 1.f); }

// ===========================================================================
// GI GEMM (R8 version, known good): g_gi/g_gip with biases folded (tf32)
// ===========================================================================
__global__ void __launch_bounds__(256) gi_gemm_k(
    const float* __restrict__ x,
    const float* __restrict__ wih,  const float* __restrict__ wihp,
    const float* __restrict__ pah,  const float* __restrict__ masks,
    const float* __restrict__ bih,  const float* __restrict__ bihp,
    const float* __restrict__ bhh,  const float* __restrict__ bhhp)
{
    constexpr int BM = 128, BN = 128, BK = 16, SA = 20;
    constexpr int WRM = 2;
    constexpr int MT = 4, NT = 4, AV = 2, BV = 2;

    __shared__ unsigned sA[2][BM * SA];
    __shared__ unsigned sB[2][BN * SA];

    const int m0 = blockIdx.y * BM;
    const int n0 = blockIdx.x * BN;
    const float* Bg = wih + (size_t)n0 * 520;

    const int tid = threadIdx.x, lane = tid & 31, warp = tid >> 5;
    const int wm = warp % WRM, wn = warp / WRM;

    float acc[MT][NT][4];
    float acc2[MT][NT][4];
#pragma unroll
    for (int i = 0; i < MT; i++)
#pragma unroll
        for (int j = 0; j < NT; j++)
#pragma unroll
            for (int q = 0; q < 4; q++) { acc[i][j][q] = 0.f; acc2[i][j][q] = 0.f; }

    unsigned ra[AV][4], rb[BV][4];

    auto GL = [&](int kc) {
#pragma unroll
        for (int i = 0; i < AV; i++) {
            int s = tid + i * 256; int r = s >> 2; int c = (s & 3) << 2;
            float4 v = *reinterpret_cast<const float4*>(x + (size_t)(m0 + r) * EE + kc * BK + c);
            ra[i][0] = f2tf(v.x); ra[i][1] = f2tf(v.y); ra[i][2] = f2tf(v.z); ra[i][3] = f2tf(v.w);
        }
#pragma unroll
        for (int i = 0; i < BV; i++) {
            int s = tid + i * 256; int r = s >> 2; int c = (s & 3) << 2;
            float4 v = *reinterpret_cast<const float4*>(Bg + (size_t)r * 520 + kc * BK + c);
            rb[i][0] = f2tf(v.x); rb[i][1] = f2tf(v.y); rb[i][2] = f2tf(v.z); rb[i][3] = f2tf(v.w);
        }
    };
    auto SS = [&](int buf) {
#pragma unroll
        for (int i = 0; i < AV; i++) {
            int s = tid + i * 256; int r = s >> 2; int c = (s & 3) << 2;
            *reinterpret_cast<uint4*>(&sA[buf][r * SA + c]) = *reinterpret_cast<uint4*>(ra[i]);
        }
#pragma unroll
        for (int i = 0; i < BV; i++) {
            int s = tid + i * 256; int r = s >> 2; int c = (s & 3) << 2;
            *reinterpret_cast<uint4*>(&sB[buf][r * SA + c]) = *reinterpret_cast<uint4*>(rb[i]);
        }
    };
    auto COMP = [&](int buf) {
#pragma unroll
        for (int k8 = 0; k8 < BK / 8; k8++) {
            unsigned af[MT][4]; unsigned bf[NT][2];
#pragma unroll
            for (int mt = 0; mt < MT; mt++) {
                int r = wm * MT * 16 + mt * 16 + (lane >> 2);
                int c = k8 * 8 + (lane & 3);
                af[mt][0] = sA[buf][r * SA + c];
                af[mt][1] = sA[buf][(r + 8) * SA + c];
                af[mt][2] = sA[buf][r * SA + c + 4];
                af[mt][3] = sA[buf][(r + 8) * SA + c + 4];
            }
#pragma unroll
            for (int nt = 0; nt < NT; nt++) {
                int n = wn * NT * 8 + nt * 8 + (lane >> 2);
                int kk = k8 * 8 + (lane & 3);
                bf[nt][0] = sB[buf][n * SA + kk];
                bf[nt][1] = sB[buf][n * SA + kk + 4];
            }
#pragma unroll
            for (int mt = 0; mt < MT; mt++)
#pragma unroll
                for (int nt = 0; nt < NT; nt++)
                    mma8(acc[mt][nt], af[mt], bf[nt]);
        }
    };

    GL(0); SS(0); __syncthreads();
    constexpr int NKC = EE / BK;
    for (int kc = 0; kc < NKC; kc++) {
        if (kc + 1 < NKC) GL(kc + 1);
        COMP(kc & 1);
        if (kc + 1 < NKC) SS((kc + 1) & 1);
        __syncthreads();
    }

    {
        int s = tid;
        if (s < BM * 2) {
            int r = s >> 1; int c = (s & 1) << 2;
            float4 v = *reinterpret_cast<const float4*>(pah + (size_t)(m0 + r) * AD + c);
            float mk = masks[m0 + r];
            uint4 t4 = { f2tf(v.x * mk), f2tf(v.y * mk), f2tf(v.z * mk), f2tf(v.w * mk) };
            *reinterpret_cast<uint4*>(&sA[0][r * SA + c]) = t4;
        }
        if (s < BN * 2) {
            int n = s >> 1; int c = (s & 1) << 2;
            float4 v = *reinterpret_cast<const float4*>(wih + (size_t)(n0 + n) * 520 + 512 + c);
            uint4 t4 = { f2tf(v.x), f2tf(v.y), f2tf(v.z), f2tf(v.w) };
            *reinterpret_cast<uint4*>(&sB[0][n * SA + c]) = t4;
            float4 w = *reinterpret_cast<const float4*>(wihp + (size_t)(n0 + n) * AD + c);
            uint4 t5 = { f2tf(w.x), f2tf(w.y), f2tf(w.z), f2tf(w.w) };
            *reinterpret_cast<uint4*>(&sB[1][n * SA + c]) = t5;
        }
    }
    __syncthreads();
    {
        unsigned af2[MT][4], b0f[NT][2], b1f[NT][2];
#pragma unroll
        for (int mt = 0; mt < MT; mt++) {
            int r = wm * MT * 16 + mt * 16 + (lane >> 2);
            int c = (lane & 3);
            af2[mt][0] = sA[0][r * SA + c];
            af2[mt][1] = sA[0][(r + 8) * SA + c];
            af2[mt][2] = sA[0][r * SA + c + 4];
            af2[mt][3] = sA[0][(r + 8) * SA + c + 4];
        }
#pragma unroll
        for (int nt = 0; nt < NT; nt++) {
            int n = wn * NT * 8 + nt * 8 + (lane >> 2);
            int kk = (lane & 3);
            b0f[nt][0] = sB[0][n * SA + kk]; b0f[nt][1] = sB[0][n * SA + kk + 4];
            b1f[nt][0] = sB[1][n * SA + kk]; b1f[nt][1] = sB[1][n * SA + kk + 4];
        }
#pragma unroll
        for (int mt = 0; mt < MT; mt++)
#pragma unroll
            for (int nt = 0; nt < NT; nt++) {
                mma8(acc[mt][nt], af2[mt], b0f[nt]);
                mma8(acc2[mt][nt], af2[mt], b1f[nt]);
            }
    }

#pragma unroll
    for (int mt = 0; mt < MT; mt++)
#pragma unroll
        for (int nt = 0; nt < NT; nt++) {
            int r = m0 + wm * MT * 16 + mt * 16 + (lane >> 2);
            int c = n0 + wn * NT * 8 + nt * 8 + ((lane & 3) << 1);
            float hb0 = (c < 1024) ? bhh[c] : 0.f;
            float hb1 = (c < 1024) ? bhh[c + 1] : 0.f;
            float b0 = bih[c] + hb0, b1 = bih[c + 1] + hb1;
            *reinterpret_cast<float2*>(&g_gi[(size_t)r * H3 + c]) =
                make_float2(acc[mt][nt][0] + b0, acc[mt][nt][1] + b1);
            *reinterpret_cast<float2*>(&g_gi[(size_t)(r + 8) * H3 + c]) =
                make_float2(acc[mt][nt][2] + b0, acc[mt][nt][3] + b1);
            float pb0 = (c < 1024) ? bhhp[c] : 0.f;
            float pb1 = (c < 1024) ? bhhp[c + 1] : 0.f;
            float p0 = bihp[c] + pb0, p1 = bihp[c + 1] + pb1;
            *reinterpret_cast<float2*>(&g_gip[(size_t)r * H3 + c]) =
                make_float2(acc2[mt][nt][0] + p0, acc2[mt][nt][1] + p1);
            *reinterpret_cast<float2*>(&g_gip[(size_t)(r + 8) * H3 + c]) =
                make_float2(acc2[mt][nt][2] + p0, acc2[mt][nt][3] + p1);
        }
}

// ===========================================================================
// Persistent scan, FP16 K=16 MMA. 128 CTAs x 256 threads, 1 CTA/SM.
// Warp grid (2 row-halves x 4 col-quarters): warp M=32, 8 j-cols x 3 gates.
// A state stored as half2 words; W SMEM-resident fp16. R8 skeleton otherwise.
// ===========================================================================
#define SW_LD 260   // u32 words per W row (256 + 4 pad), 260%32=4: conflict-free
#define SA_LD 20    // u32 words per A chunk row (16 + 4 pad), 20%32=20
#define SMEM_SCAN ((96*SW_LD + 3*64*SA_LD) * 4)

__global__ void __launch_bounds__(256, 1) scan_k(
    const float* __restrict__ whh, const float* __restrict__ whhp,
    const float* __restrict__ masks, const float* __restrict__ ginit,
    const float* __restrict__ bhh, const float* __restrict__ bhhp,
    const float* __restrict__ hxs, const float* __restrict__ hys,
    float* __restrict__ out)
{
    extern __shared__ unsigned sh[];
    unsigned* sW = sh;                      // 96 x 260 (W as half2 words)
    unsigned* sA = sh + 96 * SW_LD;         // 3 stages x 64 x 20 (A as half2 words)

    const int bx = blockIdx.x;
    const int p  = bx & 15;                 // j-slice index
    const int j0 = p * 32;
    const int m0 = ((bx >> 4) & 3) * 64;
    const int cell = bx >> 6;
    const int grp = bx >> 4;

    const float* W  = cell ? whhp : whh;
    const float* gi = cell ? g_gip : g_gi;
    const float* bh = cell ? bhhp : bhh;
    const float* hsrc = cell ? hys : hxs;
    float* outs = out + (cell ? (TNH + NH) : 0);
    float* hf   = out + (cell ? (2 * TNH + NH) : TNH);
    unsigned* bcnt = &g_bars[grp].cnt;
    unsigned* bgen = &g_bars[grp].gen;

    const int tid = threadIdx.x, lane = tid & 31, warp = tid >> 5;
    const int wm = warp & 1;      // row half (32 rows)
    const int wn = warp >> 1;     // col quarter (8 j-cols x 3 gates)

    // ---- preload weights into SMEM as fp16 (RN) ----
    for (int i = tid; i < 96 * 128; i += 256) {
        int rr = i >> 7;                  // B row (g*32 + jj)
        int f4 = i & 127;                 // float4 index within 512-col row
        int g = rr >> 5, jj = rr & 31;
        float4 v = *reinterpret_cast<const float4*>(W + (size_t)(g * HH + j0 + jj) * HH + f4 * 4);
        sW[rr * SW_LD + f4 * 2]     = pack_h2(v.x, v.y);
        sW[rr * SW_LD + f4 * 2 + 1] = pack_h2(v.z, v.w);
    }

    // ---- init own slice of A(0): global (half2) + stage0 SMEM ----
    for (int idx = tid; idx < 64 * 16; idx += 256) {
        int row = idx >> 4, cp = idx & 15;           // cp: u32 col within slice
        int n = m0 + row, c = j0 + cp * 2;
        float mk = masks[n];
        float2 hv = *reinterpret_cast<const float2*>(hsrc + (size_t)n * HH + c);
        float a0 = hv.x * mk, a1 = hv.y * mk;
        if (cell) {
            float2 gv = *reinterpret_cast<const float2*>(ginit + (size_t)n * HH + c);
            a0 += gv.x * (1.f - mk);
            a1 += gv.y * (1.f - mk);
        }
        unsigned w = pack_h2(a0, a1);
        g_A16[cell][0][(size_t)n * 256 + (j0 >> 1) + cp] = w;
        sA[row * SA_LD + cp] = w;
    }

    const int cb = j0 + wn * 8 + ((lane & 3) << 1);
    const float2 bn2 = *reinterpret_cast<const float2*>(bh + 2 * HH + cb);

    unsigned sA_u32;
    asm("{ .reg .u64 t; cvta.to.shared.u64 t, %1; cvt.u32.u64 %0, t; }"
        : "=r"(sA_u32) : "l"(sA));

    // ---- init barrier (publish A(0) slices) ----
    {
        __syncthreads();
        if (tid == 0) {
            __threadfence();
            unsigned g0;
            asm volatile("ld.acquire.gpu.u32 %0, [%1];" : "=r"(g0) : "l"(bgen));
            unsigned v = atomicAdd(bcnt, 1u);
            if (v == GSIZE - 1) {
                *bcnt = 0u;
                asm volatile("st.release.gpu.u32 [%0], %1;" :: "l"(bgen), "r"(g0 + 1u));
            } else {
                unsigned cur;
                do { asm volatile("ld.acquire.gpu.u32 %0, [%1];" : "=r"(cur) : "l"(bgen)); }
                while (cur < g0 + 1u);
            }
        }
        __syncthreads();
    }

    // ---- register-carried state hq (fp32, recomputed from inputs) ----
    float2 hq[4];
#pragma unroll
    for (int q = 0; q < 4; q++) {
        int n = m0 + wm * 32 + (q >> 1) * 16 + (lane >> 2) + (q & 1) * 8;
        float mk = masks[n];
        float2 hv = *reinterpret_cast<const float2*>(hsrc + (size_t)n * HH + cb);
        float a0 = hv.x * mk, a1 = hv.y * mk;
        if (cell) {
            float2 gv = *reinterpret_cast<const float2*>(ginit + (size_t)n * HH + cb);
            a0 += gv.x * (1.f - mk);
            a1 += gv.y * (1.f - mk);
        }
        hq[q] = make_float2(a0, a1);
    }

    // ---- initial operand prefetch: gi(0), masks(1), ginit(1) ----
    float2 pir[4], piz[4], pin[4], pg[4];
    float pmask[4];
#pragma unroll
    for (int q = 0; q < 4; q++) {
        int n = m0 + wm * 32 + (q >> 1) * 16 + (lane >> 2) + (q & 1) * 8;
        size_t gb = (size_t)n * H3 + cb;
        pmask[q] = masks[NB + n];
        pir[q] = *reinterpret_cast<const float2*>(gi + gb);
        piz[q] = *reinterpret_cast<const float2*>(gi + gb + HH);
        pin[q] = *reinterpret_cast<const float2*>(gi + gb + 2 * HH);
        pg[q] = cell ? *reinterpret_cast<const float2*>(ginit + (size_t)(NB + n) * HH + cb)
                     : make_float2(0.f, 0.f);
    }

    for (int t = 0; t < TT; t++) {
        const int rb = t & 1;
        const unsigned* Ard = g_A16[cell][rb];
        unsigned*       Awr = g_A16[cell][rb ^ 1];
        const size_t trow = (size_t)t * NB;
        const unsigned* As = Ard + (size_t)m0 * 256;

        // cp.async: one chunk (64 rows x 16 u32 = 4KB), 1 x 16B per thread
        auto issue = [&](int chunk, int stg) {
            int row = tid >> 2;
            int c4 = (tid & 3) << 2;        // u32 col (4 u32 = 16B)
            unsigned d = sA_u32 + ((((stg * 64) + row) * SA_LD + c4) << 2);
            const unsigned* src = As + (size_t)row * 256 + chunk * 16 + c4;
            asm volatile("cp.async.cg.shared.global [%0], [%1], 16;" :: "r"(d), "l"(src));
        };

        issue((p + 1) & 15, 1); asm volatile("cp.async.commit_group;");
        issue((p + 2) & 15, 2); asm volatile("cp.async.commit_group;");

        float acc[3][2][4];
#pragma unroll
        for (int g = 0; g < 3; g++)
#pragma unroll
            for (int mt = 0; mt < 2; mt++)
#pragma unroll
                for (int q = 0; q < 4; q++) acc[g][mt][q] = 0.f;

        int sr = 0;
        for (int i = 0; i < 16; i++) {
            const int chunk = (p + i) & 15;
            if (i > 0) {
                if (i < 15) asm volatile("cp.async.wait_group 1;");
                else        asm volatile("cp.async.wait_group 0;");
                __syncthreads();
                if (i <= 13) {
                    int sw = sr + 2; if (sw >= 3) sw -= 3;
                    issue((p + i + 2) & 15, sw);
                    asm volatile("cp.async.commit_group;");
                }
            }
            const unsigned* sab = sA + sr * 64 * SA_LD;
#pragma unroll
            for (int k16 = 0; k16 < 2; k16++) {
                const int ck = k16 * 8 + (lane & 3);
                unsigned af[2][4];
#pragma unroll
                for (int mt = 0; mt < 2; mt++) {
                    int r = wm * 32 + mt * 16 + (lane >> 2);
                    af[mt][0] = sab[r * SA_LD + ck];
                    af[mt][1] = sab[(r + 8) * SA_LD + ck];
                    af[mt][2] = sab[r * SA_LD + ck + 4];
                    af[mt][3] = sab[(r + 8) * SA_LD + ck + 4];
                }
                const int kg = chunk * 16 + ck;
#pragma unroll
                for (int g = 0; g < 3; g++) {
                    int bn = g * 32 + wn * 8 + (lane >> 2);
                    unsigned bf[2] = { sW[bn * SW_LD + kg], sW[bn * SW_LD + kg + 4] };
#pragma unroll
                    for (int mt = 0; mt < 2; mt++)
                        mma16h(acc[g][mt], af[mt], bf);
                }
            }
            sr++; if (sr >= 3) sr -= 3;
        }

        if (t < TT - 1) {
            __syncthreads();   // stage0 about to be overwritten by STS below

            // ---- gate math; h parked in acc[0], next-A (fp16) stored + STS'd ----
#pragma unroll
            for (int mt = 0; mt < 2; mt++)
#pragma unroll
                for (int half = 0; half < 2; half++) {
                    int q = mt * 2 + half;
                    int rowl = wm * 32 + mt * 16 + (lane >> 2) + half * 8;
                    int n = m0 + rowl;
                    float mnx = pmask[q];
                    float rr0 = fsig(pir[q].x + acc[0][mt][half * 2]);
                    float rr1 = fsig(pir[q].y + acc[0][mt][half * 2 + 1]);
                    float zz0 = fsig(piz[q].x + acc[1][mt][half * 2]);
                    float zz1 = fsig(piz[q].y + acc[1][mt][half * 2 + 1]);
                    float nn0 = ftanh(pin[q].x + rr0 * (acc[2][mt][half * 2] + bn2.x));
                    float nn1 = ftanh(pin[q].y + rr1 * (acc[2][mt][half * 2 + 1] + bn2.y));
                    float h0 = (1.f - zz0) * nn0 + zz0 * hq[q].x;
                    float h1 = (1.f - zz1) * nn1 + zz1 * hq[q].y;
                    acc[0][mt][half * 2]     = h0;
                    acc[0][mt][half * 2 + 1] = h1;
                    float a0 = h0 * mnx + pg[q].x * (1.f - mnx);
                    float a1 = h1 * mnx + pg[q].y * (1.f - mnx);
                    unsigned w = pack_h2(a0, a1);
                    Awr[(size_t)n * 256 + (cb >> 1)] = w;
                    hq[q] = make_float2(a0, a1);
                    unsigned ad = sA_u32 + ((rowl * SA_LD + wn * 4 + (lane & 3)) << 2);
                    asm volatile("st.shared.u32 [%0], %1;" :: "r"(ad), "r"(w));
                }

            // ---- arrive (non-blocking) ----
            __syncthreads();
            unsigned tgt = 0u;
            if (tid == 0) {
                __threadfence();
                unsigned g0;
                asm volatile("ld.acquire.gpu.u32 %0, [%1];" : "=r"(g0) : "l"(bgen));
                tgt = g0 + 1u;
                unsigned v = atomicAdd(bcnt, 1u);
                if (v == GSIZE - 1) {
                    *bcnt = 0u;
                    asm volatile("st.release.gpu.u32 [%0], %1;" :: "l"(bgen), "r"(tgt));
                }
            }

            // ---- shadow work: outs stores + next-step prefetch ----
#pragma unroll
            for (int mt = 0; mt < 2; mt++)
#pragma unroll
                for (int half = 0; half < 2; half++) {
                    int n = m0 + wm * 32 + mt * 16 + (lane >> 2) + half * 8;
                    *reinterpret_cast<float2*>(outs + (trow + n) * HH + cb) =
                        make_float2(acc[0][mt][half * 2], acc[0][mt][half * 2 + 1]);
                }
            const size_t trow1 = trow + NB;
            const bool hasnext2 = (t + 2 < TT);
#pragma unroll
            for (int q = 0; q < 4; q++) {
                int n = m0 + wm * 32 + (q >> 1) * 16 + (lane >> 2) + (q & 1) * 8;
                size_t gb = (trow1 + n) * (size_t)H3 + cb;
                pmask[q] = hasnext2 ? masks[trow1 + NB + n] : 0.f;
                pir[q] = *reinterpret_cast<const float2*>(gi + gb);
                piz[q] = *reinterpret_cast<const float2*>(gi + gb + HH);
                pin[q] = *reinterpret_cast<const float2*>(gi + gb + 2 * HH);
                pg[q] = (cell && hasnext2)
                    ? *reinterpret_cast<const float2*>(
                          ginit + (size_t)(trow1 + NB + n) * HH + cb)
                    : make_float2(0.f, 0.f);
            }

            // ---- wait ----
            if (tid == 0) {
                unsigned cur;
                do { asm volatile("ld.acquire.gpu.u32 %0, [%1];" : "=r"(cur) : "l"(bgen)); }
                while (cur < tgt);
            }
            __syncthreads();
        } else {
            // ---- final step: outs + final hidden state ----
#pragma unroll
            for (int mt = 0; mt < 2; mt++)
#pragma unroll
                for (int half = 0; half < 2; half++) {
                    int q = mt * 2 + half;
                    int n = m0 + wm * 32 + mt * 16 + (lane >> 2) + half * 8;
                    size_t mrow = trow + n;
                    float rr0 = fsig(pir[q].x + acc[0][mt][half * 2]);
                    float rr1 = fsig(pir[q].y + acc[0][mt][half * 2 + 1]);
                    float zz0 = fsig(piz[q].x + acc[1][mt][half * 2]);
                    float zz1 = fsig(piz[q].y + acc[1][mt][half * 2 + 1]);
                    float nn0 = ftanh(pin[q].x + rr0 * (acc[2][mt][half * 2] + bn2.x));
                    float nn1 = ftanh(pin[q].y + rr1 * (acc[2][mt][half * 2 + 1] + bn2.y));
                    float h0 = (1.f - zz0) * nn0 + zz0 * hq[q].x;
                    float h1 = (1.f - zz1) * nn1 + zz1 * hq[q].y;
                    *reinterpret_cast<float2*>(outs + mrow * HH + cb) = make_float2(h0, h1);
                    *reinterpret_cast<float2*>(hf + (size_t)n * HH + cb) = make_float2(h0, h1);
                }
        }
    }
}

extern "C" void kernel_launch(void* const* d_in, const int* in_sizes, int n_in,
                              void* d_out, int out_size)
{
    const float* x     = (const float*)d_in[0];
    const float* hxs   = (const float*)d_in[1];
    const float* hys   = (const float*)d_in[2];
    const float* ginit = (const float*)d_in[3];
    const float* masks = (const float*)d_in[4];
    const float* pah   = (const float*)d_in[5];
    const float* wih   = (const float*)d_in[6];
    const float* whh   = (const float*)d_in[7];
    const float* bih   = (const float*)d_in[8];
    const float* bhh   = (const float*)d_in[9];
    const float* wihp  = (const float*)d_in[10];
    const float* whhp  = (const float*)d_in[11];
    const float* bihp  = (const float*)d_in[12];
    const float* bhhp  = (const float*)d_in[13];
    float* out = (float*)d_out;

    gi_gemm_k<<<dim3(12, 256), 256>>>(x, wih, wihp, pah, masks, bih, bihp, bhh, bhhp);

    cudaFuncSetAttribute(scan_k, cudaFuncAttributeMaxDynamicSharedMemorySize, SMEM_SCAN);
    scan_k<<<NCTA, 256, SMEM_SCAN>>>(whh, whhp, masks, ginit, bhh, bhhp, hxs, hys, out);
}

// round 13
// speedup vs baseline: 1.4801x; 1.0837x over previous
#include <cuda_runtime.h>
#include <cuda_fp16.h>
#include <math.h>

#define TT 128
#define NB 256
#define EE 512
#define AD 8
#define HH 512
#define H3 1536
#define TN (TT*NB)
#define TNH ((size_t)TN*HH)
#define NH (NB*HH)
#define NCTA 128
#define NGROUP 8
#define GSIZE 16

// Scratch (no cudaMalloc allowed)
__device__ float g_gi [(size_t)TN * H3];
__device__ float g_gip[(size_t)TN * H3];
__device__ unsigned g_A16[2][2][NH/2];     // masked hidden state as half2 words
struct __align__(128) Bar { unsigned cnt; unsigned gen; unsigned pad[30]; };
__device__ Bar g_bars[NGROUP];

__device__ __forceinline__ unsigned pack_h2(float a, float b) {
    __half2 h = __floats2half2_rn(a, b);
    return *reinterpret_cast<unsigned*>(&h);
}

// fp16 m16n8k16, fp32 accumulate
__device__ __forceinline__ void mma16h(float* c, const unsigned* a, const unsigned* b) {
    asm volatile(
        "mma.sync.aligned.m16n8k16.row.col.f32.f16.f16.f32 "
        "{%0,%1,%2,%3},{%4,%5,%6,%7},{%8,%9},{%0,%1,%2,%3};"
        : "+f"(c[0]), "+f"(c[1]), "+f"(c[2]), "+f"(c[3])
        : "r"(a[0]), "r"(a[1]), "r"(a[2]), "r"(a[3]), "r"(b[0]), "r"(b[1]));
}

__device__ __forceinline__ float fsig(float x) { return 1.f / (1.f + __expf(-x)); }
__device__ __forceinline__ float ftanh(float x) { return 1.f - 2.f / (__expf(2.f * x) + 1.f); }

// ===========================================================================
// GI GEMM, fp16 operands / fp32 accumulate. BK=32 (2 k16 per chunk).
// ===========================================================================
__global__ void __launch_bounds__(256) gi_gemm_k(
    const float* __restrict__ x,
    const float* __restrict__ wih,  const float* __restrict__ wihp,
    const float* __restrict__ pah,  const float* __restrict__ masks,
    const float* __restrict__ bih,  const float* __restrict__ bihp,
    const float* __restrict__ bhh,  const float* __restrict__ bhhp)
{
    constexpr int SAH = 20;   // u32 per row: 16 data + 4 pad
    __shared__ unsigned sA[2][128 * SAH];
    __shared__ unsigned sB[2][128 * SAH];

    const int m0 = blockIdx.y * 128;
    const int n0 = blockIdx.x * 128;
    const float* Bg = wih + (size_t)n0 * 520;

    const int tid = threadIdx.x, lane = tid & 31, warp = tid >> 5;
    const int wm = warp & 1, wn = warp >> 1;   // wm: 64-row half; wn: 32-col quarter

    float acc[4][4][4];
#pragma unroll
    for (int i = 0; i < 4; i++)
#pragma unroll
        for (int j = 0; j < 4; j++)
#pragma unroll
            for (int q = 0; q < 4; q++) acc[i][j][q] = 0.f;

    unsigned ra[4][2], rb[4][2];

    auto GL = [&](int kc) {
#pragma unroll
        for (int i = 0; i < 4; i++) {
            int s = tid + i * 256; int r = s >> 3; int c4 = (s & 7) << 2;
            float4 v = *reinterpret_cast<const float4*>(x + (size_t)(m0 + r) * EE + kc * 32 + c4);
            ra[i][0] = pack_h2(v.x, v.y); ra[i][1] = pack_h2(v.z, v.w);
            float4 w = *reinterpret_cast<const float4*>(Bg + (size_t)r * 520 + kc * 32 + c4);
            rb[i][0] = pack_h2(w.x, w.y); rb[i][1] = pack_h2(w.z, w.w);
        }
    };
    auto SS = [&](int buf) {
#pragma unroll
        for (int i = 0; i < 4; i++) {
            int s = tid + i * 256; int r = s >> 3; int c2 = (s & 7) << 1;
            sA[buf][r * SAH + c2]     = ra[i][0];
            sA[buf][r * SAH + c2 + 1] = ra[i][1];
            sB[buf][r * SAH + c2]     = rb[i][0];
            sB[buf][r * SAH + c2 + 1] = rb[i][1];
        }
    };
    auto COMP = [&](int buf) {
#pragma unroll
        for (int k16 = 0; k16 < 2; k16++) {
            const int ck = k16 * 8 + (lane & 3);
            unsigned af[4][4]; unsigned bf[4][2];
#pragma unroll
            for (int mt = 0; mt < 4; mt++) {
                int r = wm * 64 + mt * 16 + (lane >> 2);
                af[mt][0] = sA[buf][r * SAH + ck];
                af[mt][1] = sA[buf][(r + 8) * SAH + ck];
                af[mt][2] = sA[buf][r * SAH + ck + 4];
                af[mt][3] = sA[buf][(r + 8) * SAH + ck + 4];
            }
#pragma unroll
            for (int nt = 0; nt < 4; nt++) {
                int n = wn * 32 + nt * 8 + (lane >> 2);
                bf[nt][0] = sB[buf][n * SAH + ck];
                bf[nt][1] = sB[buf][n * SAH + ck + 4];
            }
#pragma unroll
            for (int mt = 0; mt < 4; mt++)
#pragma unroll
                for (int nt = 0; nt < 4; nt++)
                    mma16h(acc[mt][nt], af[mt], bf[nt]);
        }
    };

    GL(0); SS(0); __syncthreads();
    constexpr int NKC = EE / 32;    // 16
    for (int kc = 0; kc < NKC; kc++) {
        if (kc + 1 < NKC) GL(kc + 1);
        COMP(kc & 1);
        if (kc + 1 < NKC) SS((kc + 1) & 1);
        __syncthreads();
    }

    // Tail: masked prev-action (K=8, zero-padded to one k16)
    {
        int r = tid >> 1, hi = tid & 1;     // 256 threads: 2 per row
        float mk = masks[m0 + r];
        float4 v = *reinterpret_cast<const float4*>(pah + (size_t)(m0 + r) * AD + hi * 4);
        sA[0][r * SAH + hi * 2]     = pack_h2(v.x * mk, v.y * mk);
        sA[0][r * SAH + hi * 2 + 1] = pack_h2(v.z * mk, v.w * mk);
        sA[0][r * SAH + 4 + hi * 2]     = 0u;
        sA[0][r * SAH + 4 + hi * 2 + 1] = 0u;
        float4 w = *reinterpret_cast<const float4*>(wih + (size_t)(n0 + r) * 520 + 512 + hi * 4);
        sB[0][r * SAH + hi * 2]     = pack_h2(w.x, w.y);
        sB[0][r * SAH + hi * 2 + 1] = pack_h2(w.z, w.w);
        sB[0][r * SAH + 4 + hi * 2]     = 0u;
        sB[0][r * SAH + 4 + hi * 2 + 1] = 0u;
        float4 u = *reinterpret_cast<const float4*>(wihp + (size_t)(n0 + r) * AD + hi * 4);
        sB[1][r * SAH + hi * 2]     = pack_h2(u.x, u.y);
        sB[1][r * SAH + hi * 2 + 1] = pack_h2(u.z, u.w);
        sB[1][r * SAH + 4 + hi * 2]     = 0u;
        sB[1][r * SAH + 4 + hi * 2 + 1] = 0u;
    }
    __syncthreads();
    {
        const int ck = (lane & 3);
        unsigned af2[4][4], b0f[4][2], b1f[4][2];
#pragma unroll
        for (int mt = 0; mt < 4; mt++) {
            int r = wm * 64 + mt * 16 + (lane >> 2);
            af2[mt][0] = sA[0][r * SAH + ck];
            af2[mt][1] = sA[0][(r + 8) * SAH + ck];
            af2[mt][2] = sA[0][r * SAH + ck + 4];
            af2[mt][3] = sA[0][(r + 8) * SAH + ck + 4];
        }
#pragma unroll
        for (int nt = 0; nt < 4; nt++) {
            int n = wn * 32 + nt * 8 + (lane >> 2);
            b0f[nt][0] = sB[0][n * SAH + ck]; b0f[nt][1] = sB[0][n * SAH + ck + 4];
            b1f[nt][0] = sB[1][n * SAH + ck]; b1f[nt][1] = sB[1][n * SAH + ck + 4];
        }
#pragma unroll
        for (int mt = 0; mt < 4; mt++)
#pragma unroll
            for (int nt = 0; nt < 4; nt++) {
                mma16h(acc[mt][nt], af2[mt], b0f[nt]);
                float acc2l[4] = {0.f, 0.f, 0.f, 0.f};
                mma16h(acc2l, af2[mt], b1f[nt]);

                int r = m0 + wm * 64 + mt * 16 + (lane >> 2);
                int c = n0 + wn * 32 + nt * 8 + ((lane & 3) << 1);
                float hb0 = (c < 1024) ? bhh[c] : 0.f;
                float hb1 = (c < 1024) ? bhh[c + 1] : 0.f;
                float b0 = bih[c] + hb0, b1 = bih[c + 1] + hb1;
                *reinterpret_cast<float2*>(&g_gi[(size_t)r * H3 + c]) =
                    make_float2(acc[mt][nt][0] + b0, acc[mt][nt][1] + b1);
                *reinterpret_cast<float2*>(&g_gi[(size_t)(r + 8) * H3 + c]) =
                    make_float2(acc[mt][nt][2] + b0, acc[mt][nt][3] + b1);
                float pb0 = (c < 1024) ? bhhp[c] : 0.f;
                float pb1 = (c < 1024) ? bhhp[c + 1] : 0.f;
                float p0 = bihp[c] + pb0, p1 = bihp[c + 1] + pb1;
                *reinterpret_cast<float2*>(&g_gip[(size_t)r * H3 + c]) =
                    make_float2(acc2l[0] + p0, acc2l[1] + p1);
                *reinterpret_cast<float2*>(&g_gip[(size_t)(r + 8) * H3 + c]) =
                    make_float2(acc2l[2] + p0, acc2l[3] + p1);
            }
    }
}

// ===========================================================================
// Persistent scan, FP16 K=16 MMA, BK=64 (8 pipeline iterations/step).
// 128 CTAs x 256 threads; warp grid (2 row-halves x 4 col-quarters).
// ===========================================================================
#define SW_LD 260   // u32 per W row (256 + 4 pad)
#define SA_LD 36    // u32 per A chunk row (32 + 4 pad)
#define SMEM_SCAN ((96*SW_LD + 3*64*SA_LD) * 4)

__global__ void __launch_bounds__(256, 1) scan_k(
    const float* __restrict__ whh, const float* __restrict__ whhp,
    const float* __restrict__ masks, const float* __restrict__ ginit,
    const float* __restrict__ bhh, const float* __restrict__ bhhp,
    const float* __restrict__ hxs, const float* __restrict__ hys,
    float* __restrict__ out)
{
    extern __shared__ unsigned sh[];
    unsigned* sW = sh;                      // 96 x 260 (W as half2 words)
    unsigned* sA = sh + 96 * SW_LD;         // 3 stages x 64 x 36

    const int bx = blockIdx.x;
    const int p  = bx & 15;
    const int j0 = p * 32;
    const int m0 = ((bx >> 4) & 3) * 64;
    const int cell = bx >> 6;
    const int grp = bx >> 4;
    const int c0 = p >> 1;                  // ring start chunk (near own slice)

    const float* W  = cell ? whhp : whh;
    const float* gi = cell ? g_gip : g_gi;
    const float* bh = cell ? bhhp : bhh;
    const float* hsrc = cell ? hys : hxs;
    float* outs = out + (cell ? (TNH + NH) : 0);
    float* hf   = out + (cell ? (2 * TNH + NH) : TNH);
    unsigned* bcnt = &g_bars[grp].cnt;
    unsigned* bgen = &g_bars[grp].gen;

    const int tid = threadIdx.x, lane = tid & 31, warp = tid >> 5;
    const int wm = warp & 1;
    const int wn = warp >> 1;

    // ---- preload weights into SMEM as fp16 ----
    for (int i = tid; i < 96 * 128; i += 256) {
        int rr = i >> 7;
        int f4 = i & 127;
        int g = rr >> 5, jj = rr & 31;
        float4 v = *reinterpret_cast<const float4*>(W + (size_t)(g * HH + j0 + jj) * HH + f4 * 4);
        sW[rr * SW_LD + f4 * 2]     = pack_h2(v.x, v.y);
        sW[rr * SW_LD + f4 * 2 + 1] = pack_h2(v.z, v.w);
    }

    // ---- init own slice of A(0) (global, half2 words) ----
    for (int idx = tid; idx < 64 * 16; idx += 256) {
        int row = idx >> 4, cp = idx & 15;
        int n = m0 + row, c = j0 + cp * 2;
        float mk = masks[n];
        float2 hv = *reinterpret_cast<const float2*>(hsrc + (size_t)n * HH + c);
        float a0 = hv.x * mk, a1 = hv.y * mk;
        if (cell) {
            float2 gv = *reinterpret_cast<const float2*>(ginit + (size_t)n * HH + c);
            a0 += gv.x * (1.f - mk);
            a1 += gv.y * (1.f - mk);
        }
        g_A16[cell][0][(size_t)n * 256 + (j0 >> 1) + cp] = pack_h2(a0, a1);
    }

    const int cb = j0 + wn * 8 + ((lane & 3) << 1);
    const float2 bn2 = *reinterpret_cast<const float2*>(bh + 2 * HH + cb);

    unsigned sA_u32;
    asm("{ .reg .u64 t; cvta.to.shared.u64 t, %1; cvt.u32.u64 %0, t; }"
        : "=r"(sA_u32) : "l"(sA));

    // ---- init barrier (publish A(0) slices) ----
    {
        __syncthreads();
        if (tid == 0) {
            __threadfence();
            unsigned g0;
            asm volatile("ld.acquire.gpu.u32 %0, [%1];" : "=r"(g0) : "l"(bgen));
            unsigned v = atomicAdd(bcnt, 1u);
            if (v == GSIZE - 1) {
                *bcnt = 0u;
                asm volatile("st.release.gpu.u32 [%0], %1;" :: "l"(bgen), "r"(g0 + 1u));
            } else {
                unsigned cur;
                do { asm volatile("ld.acquire.gpu.u32 %0, [%1];" : "=r"(cur) : "l"(bgen)); }
                while (cur < g0 + 1u);
            }
        }
        __syncthreads();
    }

    // ---- register-carried state hq (fp32) ----
    float2 hq[4];
#pragma unroll
    for (int q = 0; q < 4; q++) {
        int n = m0 + wm * 32 + (q >> 1) * 16 + (lane >> 2) + (q & 1) * 8;
        float mk = masks[n];
        float2 hv = *reinterpret_cast<const float2*>(hsrc + (size_t)n * HH + cb);
        float a0 = hv.x * mk, a1 = hv.y * mk;
        if (cell) {
            float2 gv = *reinterpret_cast<const float2*>(ginit + (size_t)n * HH + cb);
            a0 += gv.x * (1.f - mk);
            a1 += gv.y * (1.f - mk);
        }
        hq[q] = make_float2(a0, a1);
    }

    // ---- initial operand prefetch ----
    float2 pir[4], piz[4], pin[4], pg[4];
    float pmask[4];
#pragma unroll
    for (int q = 0; q < 4; q++) {
        int n = m0 + wm * 32 + (q >> 1) * 16 + (lane >> 2) + (q & 1) * 8;
        size_t gb = (size_t)n * H3 + cb;
        pmask[q] = masks[NB + n];
        pir[q] = *reinterpret_cast<const float2*>(gi + gb);
        piz[q] = *reinterpret_cast<const float2*>(gi + gb + HH);
        pin[q] = *reinterpret_cast<const float2*>(gi + gb + 2 * HH);
        pg[q] = cell ? *reinterpret_cast<const float2*>(ginit + (size_t)(NB + n) * HH + cb)
                     : make_float2(0.f, 0.f);
    }

    for (int t = 0; t < TT; t++) {
        const int rb = t & 1;
        const unsigned* Ard = g_A16[cell][rb];
        unsigned*       Awr = g_A16[cell][rb ^ 1];
        const size_t trow = (size_t)t * NB;
        const unsigned* As = Ard + (size_t)m0 * 256;

        // cp.async: one chunk (64 rows x 32 u32 = 8KB), 2 x 16B per thread
        auto issue = [&](int chunk, int stg) {
#pragma unroll
            for (int pp = 0; pp < 2; pp++) {
                int e = tid + pp * 256;
                int row = e >> 3;
                int c4 = (e & 7) << 2;
                unsigned d = sA_u32 + ((((stg * 64) + row) * SA_LD + c4) << 2);
                const unsigned* src = As + (size_t)row * 256 + chunk * 32 + c4;
                asm volatile("cp.async.cg.shared.global [%0], [%1], 16;" :: "r"(d), "l"(src));
            }
            asm volatile("cp.async.commit_group;");
        };

        issue(c0 & 7, 0);
        issue((c0 + 1) & 7, 1);
        issue((c0 + 2) & 7, 2);

        float acc[3][2][4];
#pragma unroll
        for (int g = 0; g < 3; g++)
#pragma unroll
            for (int mt = 0; mt < 2; mt++)
#pragma unroll
                for (int q = 0; q < 4; q++) acc[g][mt][q] = 0.f;

        for (int i = 0; i < 8; i++) {
            const int chunk = (c0 + i) & 7;
            const int sr = i % 3;
            if (i == 0) {
                asm volatile("cp.async.wait_group 2;");
                __syncthreads();
            } else {
                asm volatile("cp.async.wait_group 1;");
                __syncthreads();
                if (i + 2 < 8) issue((c0 + i + 2) & 7, (i - 1) % 3);
                else           asm volatile("cp.async.commit_group;");
            }
            const unsigned* sab = sA + sr * 64 * SA_LD;
#pragma unroll
            for (int k16 = 0; k16 < 4; k16++) {
                const int ck = k16 * 8 + (lane & 3);
                unsigned af[2][4];
#pragma unroll
                for (int mt = 0; mt < 2; mt++) {
                    int r = wm * 32 + mt * 16 + (lane >> 2);
                    af[mt][0] = sab[r * SA_LD + ck];
                    af[mt][1] = sab[(r + 8) * SA_LD + ck];
                    af[mt][2] = sab[r * SA_LD + ck + 4];
                    af[mt][3] = sab[(r + 8) * SA_LD + ck + 4];
                }
                const int kg = chunk * 32 + k16 * 8 + (lane & 3);
#pragma unroll
                for (int g = 0; g < 3; g++) {
                    int bn = g * 32 + wn * 8 + (lane >> 2);
                    unsigned bf[2] = { sW[bn * SW_LD + kg], sW[bn * SW_LD + kg + 4] };
#pragma unroll
                    for (int mt = 0; mt < 2; mt++)
                        mma16h(acc[g][mt], af[mt], bf);
                }
            }
        }

        if (t < TT - 1) {
            // ---- gate math; h parked in acc[0], next-A (fp16) to global ----
#pragma unroll
            for (int mt = 0; mt < 2; mt++)
#pragma unroll
                for (int half = 0; half < 2; half++) {
                    int q = mt * 2 + half;
                    int n = m0 + wm * 32 + mt * 16 + (lane >> 2) + half * 8;
                    float mnx = pmask[q];
                    float rr0 = fsig(pir[q].x + acc[0][mt][half * 2]);
                    float rr1 = fsig(pir[q].y + acc[0][mt][half * 2 + 1]);
                    float zz0 = fsig(piz[q].x + acc[1][mt][half * 2]);
                    float zz1 = fsig(piz[q].y + acc[1][mt][half * 2 + 1]);
                    float nn0 = ftanh(pin[q].x + rr0 * (acc[2][mt][half * 2] + bn2.x));
                    float nn1 = ftanh(pin[q].y + rr1 * (acc[2][mt][half * 2 + 1] + bn2.y));
                    float h0 = (1.f - zz0) * nn0 + zz0 * hq[q].x;
                    float h1 = (1.f - zz1) * nn1 + zz1 * hq[q].y;
                    acc[0][mt][half * 2]     = h0;
                    acc[0][mt][half * 2 + 1] = h1;
                    float a0 = h0 * mnx + pg[q].x * (1.f - mnx);
                    float a1 = h1 * mnx + pg[q].y * (1.f - mnx);
                    Awr[(size_t)n * 256 + (cb >> 1)] = pack_h2(a0, a1);
                    hq[q] = make_float2(a0, a1);
                }

            // ---- arrive (non-blocking) ----
            __syncthreads();
            unsigned tgt = 0u;
            if (tid == 0) {
                __threadfence();
                unsigned g0;
                asm volatile("ld.acquire.gpu.u32 %0, [%1];" : "=r"(g0) : "l"(bgen));
                tgt = g0 + 1u;
                unsigned v = atomicAdd(bcnt, 1u);
                if (v == GSIZE - 1) {
                    *bcnt = 0u;
                    asm volatile("st.release.gpu.u32 [%0], %1;" :: "l"(bgen), "r"(tgt));
                }
            }

            // ---- shadow work: outs stores + next-step prefetch ----
#pragma unroll
            for (int mt = 0; mt < 2; mt++)
#pragma unroll
                for (int half = 0; half < 2; half++) {
                    int n = m0 + wm * 32 + mt * 16 + (lane >> 2) + half * 8;
                    *reinterpret_cast<float2*>(outs + (trow + n) * HH + cb) =
                        make_float2(acc[0][mt][half * 2], acc[0][mt][half * 2 + 1]);
                }
            const size_t trow1 = trow + NB;
            const bool hasnext2 = (t + 2 < TT);
#pragma unroll
            for (int q = 0; q < 4; q++) {
                int n = m0 + wm * 32 + (q >> 1) * 16 + (lane >> 2) + (q & 1) * 8;
                size_t gb = (trow1 + n) * (size_t)H3 + cb;
                pmask[q] = hasnext2 ? masks[trow1 + NB + n] : 0.f;
                pir[q] = *reinterpret_cast<const float2*>(gi + gb);
                piz[q] = *reinterpret_cast<const float2*>(gi + gb + HH);
                pin[q] = *reinterpret_cast<const float2*>(gi + gb + 2 * HH);
                pg[q] = (cell && hasnext2)
                    ? *reinterpret_cast<const float2*>(
                          ginit + (size_t)(trow1 + NB + n) * HH + cb)
                    : make_float2(0.f, 0.f);
            }

            // ---- wait ----
            if (tid == 0) {
                unsigned cur;
                do { asm volatile("ld.acquire.gpu.u32 %0, [%1];" : "=r"(cur) : "l"(bgen)); }
                while (cur < tgt);
            }
            __syncthreads();
        } else {
            // ---- final step ----
#pragma unroll
            for (int mt = 0; mt < 2; mt++)
#pragma unroll
                for (int half = 0; half < 2; half++) {
                    int q = mt * 2 + half;
                    int n = m0 + wm * 32 + mt * 16 + (lane >> 2) + half * 8;
                    size_t mrow = trow + n;
                    float rr0 = fsig(pir[q].x + acc[0][mt][half * 2]);
                    float rr1 = fsig(pir[q].y + acc[0][mt][half * 2 + 1]);
                    float zz0 = fsig(piz[q].x + acc[1][mt][half * 2]);
                    float zz1 = fsig(piz[q].y + acc[1][mt][half * 2 + 1]);
                    float nn0 = ftanh(pin[q].x + rr0 * (acc[2][mt][half * 2] + bn2.x));
                    float nn1 = ftanh(pin[q].y + rr1 * (acc[2][mt][half * 2 + 1] + bn2.y));
                    float h0 = (1.f - zz0) * nn0 + zz0 * hq[q].x;
                    float h1 = (1.f - zz1) * nn1 + zz1 * hq[q].y;
                    *reinterpret_cast<float2*>(outs + mrow * HH + cb) = make_float2(h0, h1);
                    *reinterpret_cast<float2*>(hf + (size_t)n * HH + cb) = make_float2(h0, h1);
                }
        }
    }
}

extern "C" void kernel_launch(void* const* d_in, const int* in_sizes, int n_in,
                              void* d_out, int out_size)
{
    const float* x     = (const float*)d_in[0];
    const float* hxs   = (const float*)d_in[1];
    const float* hys   = (const float*)d_in[2];
    const float* ginit = (const float*)d_in[3];
    const float* masks = (const float*)d_in[4];
    const float* pah   = (const float*)d_in[5];
    const float* wih   = (const float*)d_in[6];
    const float* whh   = (const float*)d_in[7];
    const float* bih   = (const float*)d_in[8];
    const float* bhh   = (const float*)d_in[9];
    const float* wihp  = (const float*)d_in[10];
    const float* whhp  = (const float*)d_in[11];
    const float* bihp  = (const float*)d_in[12];
    const float* bhhp  = (const float*)d_in[13];
    float* out = (float*)d_out;

    gi_gemm_k<<<dim3(12, 256), 256>>>(x, wih, wihp, pah, masks, bih, bihp, bhh, bhhp);

    cudaFuncSetAttribute(scan_k, cudaFuncAttributeMaxDynamicSharedMemorySize, SMEM_SCAN);
    scan_k<<<NCTA, 256, SMEM_SCAN>>>(whh, whhp, masks, ginit, bhh, bhhp, hxs, hys, out);
}

// round 15
// speedup vs baseline: 1.5362x; 1.0379x over previous
#include <cuda_runtime.h>
#include <cuda_fp16.h>
#include <math.h>

#define TT 128
#define NB 256
#define EE 512
#define AD 8
#define HH 512
#define H3 1536
#define TN (TT*NB)
#define TNH ((size_t)TN*HH)
#define NH (NB*HH)
#define NCTA 128
#define NGROUP 8
#define GSIZE 16

// Scratch (no cudaMalloc allowed)
__device__ float g_gi [(size_t)TN * H3];
__device__ float g_gip[(size_t)TN * H3];
__device__ unsigned g_A16[2][2][NH/2];     // masked hidden state as half2 words
struct __align__(128) Bar { unsigned cnt; unsigned gen; unsigned pad[30]; };
__device__ Bar g_bars[NGROUP];

__device__ __forceinline__ unsigned pack_h2(float a, float b) {
    __half2 h = __floats2half2_rn(a, b);
    return *reinterpret_cast<unsigned*>(&h);
}

// fp16 m16n8k16, fp32 accumulate
__device__ __forceinline__ void mma16h(float* c, const unsigned* a, const unsigned* b) {
    asm volatile(
        "mma.sync.aligned.m16n8k16.row.col.f32.f16.f16.f32 "
        "{%0,%1,%2,%3},{%4,%5,%6,%7},{%8,%9},{%0,%1,%2,%3};"
        : "+f"(c[0]), "+f"(c[1]), "+f"(c[2]), "+f"(c[3])
        : "r"(a[0]), "r"(a[1]), "r"(a[2]), "r"(a[3]), "r"(b[0]), "r"(b[1]));
}

__device__ __forceinline__ float fsig(float x) { return 1.f / (1.f + __expf(-x)); }
__device__ __forceinline__ float ftanh(float x) { return 1.f - 2.f / (__expf(2.f * x) + 1.f); }

__device__ __forceinline__ void mbar_wait(unsigned mb, unsigned parity) {
    unsigned done;
    asm volatile(
        "{\n\t.reg .pred p;\n\t"
        "mbarrier.try_wait.parity.acquire.cta.shared::cta.b64 p, [%1], %2;\n\t"
        "selp.b32 %0, 1, 0, p;\n\t}"
        : "=r"(done) : "r"(mb), "r"(parity) : "memory");
    if (!done) {
        asm volatile(
            "{\n\t.reg .pred P1;\n\t"
            "W_%=:\n\t"
            "mbarrier.try_wait.parity.acquire.cta.shared::cta.b64 P1, [%0], %1, 0x989680;\n\t"
            "@P1 bra.uni D_%=;\n\t"
            "bra.uni W_%=;\n\t"
            "D_%=:\n\t}"
            :: "r"(mb), "r"(parity) : "memory");
    }
}

// ===========================================================================
// GI GEMM, fp16 operands / fp32 accumulate (R13, known good).
// ===========================================================================
__global__ void __launch_bounds__(256) gi_gemm_k(
    const float* __restrict__ x,
    const float* __restrict__ wih,  const float* __restrict__ wihp,
    const float* __restrict__ pah,  const float* __restrict__ masks,
    const float* __restrict__ bih,  const float* __restrict__ bihp,
    const float* __restrict__ bhh,  const float* __restrict__ bhhp)
{
    constexpr int SAH = 20;
    __shared__ unsigned sA[2][128 * SAH];
    __shared__ unsigned sB[2][128 * SAH];

    const int m0 = blockIdx.y * 128;
    const int n0 = blockIdx.x * 128;
    const float* Bg = wih + (size_t)n0 * 520;

    const int tid = threadIdx.x, lane = tid & 31, warp = tid >> 5;
    const int wm = warp & 1, wn = warp >> 1;

    float acc[4][4][4];
#pragma unroll
    for (int i = 0; i < 4; i++)
#pragma unroll
        for (int j = 0; j < 4; j++)
#pragma unroll
            for (int q = 0; q < 4; q++) acc[i][j][q] = 0.f;

    unsigned ra[4][2], rb[4][2];

    auto GL = [&](int kc) {
#pragma unroll
        for (int i = 0; i < 4; i++) {
            int s = tid + i * 256; int r = s >> 3; int c4 = (s & 7) << 2;
            float4 v = *reinterpret_cast<const float4*>(x + (size_t)(m0 + r) * EE + kc * 32 + c4);
            ra[i][0] = pack_h2(v.x, v.y); ra[i][1] = pack_h2(v.z, v.w);
            float4 w = *reinterpret_cast<const float4*>(Bg + (size_t)r * 520 + kc * 32 + c4);
            rb[i][0] = pack_h2(w.x, w.y); rb[i][1] = pack_h2(w.z, w.w);
        }
    };
    auto SS = [&](int buf) {
#pragma unroll
        for (int i = 0; i < 4; i++) {
            int s = tid + i * 256; int r = s >> 3; int c2 = (s & 7) << 1;
            sA[buf][r * SAH + c2]     = ra[i][0];
            sA[buf][r * SAH + c2 + 1] = ra[i][1];
            sB[buf][r * SAH + c2]     = rb[i][0];
            sB[buf][r * SAH + c2 + 1] = rb[i][1];
        }
    };
    auto COMP = [&](int buf) {
#pragma unroll
        for (int k16 = 0; k16 < 2; k16++) {
            const int ck = k16 * 8 + (lane & 3);
            unsigned af[4][4]; unsigned bf[4][2];
#pragma unroll
            for (int mt = 0; mt < 4; mt++) {
                int r = wm * 64 + mt * 16 + (lane >> 2);
                af[mt][0] = sA[buf][r * SAH + ck];
                af[mt][1] = sA[buf][(r + 8) * SAH + ck];
                af[mt][2] = sA[buf][r * SAH + ck + 4];
                af[mt][3] = sA[buf][(r + 8) * SAH + ck + 4];
            }
#pragma unroll
            for (int nt = 0; nt < 4; nt++) {
                int n = wn * 32 + nt * 8 + (lane >> 2);
                bf[nt][0] = sB[buf][n * SAH + ck];
                bf[nt][1] = sB[buf][n * SAH + ck + 4];
            }
#pragma unroll
            for (int mt = 0; mt < 4; mt++)
#pragma unroll
                for (int nt = 0; nt < 4; nt++)
                    mma16h(acc[mt][nt], af[mt], bf[nt]);
        }
    };

    GL(0); SS(0); __syncthreads();
    constexpr int NKC = EE / 32;
    for (int kc = 0; kc < NKC; kc++) {
        if (kc + 1 < NKC) GL(kc + 1);
        COMP(kc & 1);
        if (kc + 1 < NKC) SS((kc + 1) & 1);
        __syncthreads();
    }

    {
        int r = tid >> 1, hi = tid & 1;
        float mk = masks[m0 + r];
        float4 v = *reinterpret_cast<const float4*>(pah + (size_t)(m0 + r) * AD + hi * 4);
        sA[0][r * SAH + hi * 2]     = pack_h2(v.x * mk, v.y * mk);
        sA[0][r * SAH + hi * 2 + 1] = pack_h2(v.z * mk, v.w * mk);
        sA[0][r * SAH + 4 + hi * 2]     = 0u;
        sA[0][r * SAH + 4 + hi * 2 + 1] = 0u;
        float4 w = *reinterpret_cast<const float4*>(wih + (size_t)(n0 + r) * 520 + 512 + hi * 4);
        sB[0][r * SAH + hi * 2]     = pack_h2(w.x, w.y);
        sB[0][r * SAH + hi * 2 + 1] = pack_h2(w.z, w.w);
        sB[0][r * SAH + 4 + hi * 2]     = 0u;
        sB[0][r * SAH + 4 + hi * 2 + 1] = 0u;
        float4 u = *reinterpret_cast<const float4*>(wihp + (size_t)(n0 + r) * AD + hi * 4);
        sB[1][r * SAH + hi * 2]     = pack_h2(u.x, u.y);
        sB[1][r * SAH + hi * 2 + 1] = pack_h2(u.z, u.w);
        sB[1][r * SAH + 4 + hi * 2]     = 0u;
        sB[1][r * SAH + 4 + hi * 2 + 1] = 0u;
    }
    __syncthreads();
    {
        const int ck = (lane & 3);
        unsigned af2[4][4], b0f[4][2], b1f[4][2];
#pragma unroll
        for (int mt = 0; mt < 4; mt++) {
            int r = wm * 64 + mt * 16 + (lane >> 2);
            af2[mt][0] = sA[0][r * SAH + ck];
            af2[mt][1] = sA[0][(r + 8) * SAH + ck];
            af2[mt][2] = sA[0][r * SAH + ck + 4];
            af2[mt][3] = sA[0][(r + 8) * SAH + ck + 4];
        }
#pragma unroll
        for (int nt = 0; nt < 4; nt++) {
            int n = wn * 32 + nt * 8 + (lane >> 2);
            b0f[nt][0] = sB[0][n * SAH + ck]; b0f[nt][1] = sB[0][n * SAH + ck + 4];
            b1f[nt][0] = sB[1][n * SAH + ck]; b1f[nt][1] = sB[1][n * SAH + ck + 4];
        }
#pragma unroll
        for (int mt = 0; mt < 4; mt++)
#pragma unroll
            for (int nt = 0; nt < 4; nt++) {
                mma16h(acc[mt][nt], af2[mt], b0f[nt]);
                float acc2l[4] = {0.f, 0.f, 0.f, 0.f};
                mma16h(acc2l, af2[mt], b1f[nt]);

                int r = m0 + wm * 64 + mt * 16 + (lane >> 2);
                int c = n0 + wn * 32 + nt * 8 + ((lane & 3) << 1);
                float hb0 = (c < 1024) ? bhh[c] : 0.f;
                float hb1 = (c < 1024) ? bhh[c + 1] : 0.f;
                float b0 = bih[c] + hb0, b1 = bih[c + 1] + hb1;
                *reinterpret_cast<float2*>(&g_gi[(size_t)r * H3 + c]) =
                    make_float2(acc[mt][nt][0] + b0, acc[mt][nt][1] + b1);
                *reinterpret_cast<float2*>(&g_gi[(size_t)(r + 8) * H3 + c]) =
                    make_float2(acc[mt][nt][2] + b0, acc[mt][nt][3] + b1);
                float pb0 = (c < 1024) ? bhhp[c] : 0.f;
                float pb1 = (c < 1024) ? bhhp[c + 1] : 0.f;
                float p0 = bihp[c] + pb0, p1 = bihp[c + 1] + pb1;
                *reinterpret_cast<float2*>(&g_gip[(size_t)r * H3 + c]) =
                    make_float2(acc2l[0] + p0, acc2l[1] + p1);
                *reinterpret_cast<float2*>(&g_gip[(size_t)(r + 8) * H3 + c]) =
                    make_float2(acc2l[2] + p0, acc2l[3] + p1);
            }
    }
}

// ===========================================================================
// Persistent scan, FP16 K=16 MMA, 8 fully-prefetched stages, mbarrier-tracked
// cp.async via .noinc arrives (no __syncthreads in the k-loop).
// 128 CTAs x 256 threads.
// ===========================================================================
#define SW_LD 260   // u32 per W row
#define SA_LD 36    // u32 per A chunk row
#define MB_U32 16                           // 8 mbarriers (64 B)
#define SMEM_SCAN ((MB_U32 + 96*SW_LD + 8*64*SA_LD) * 4)

__global__ void __launch_bounds__(256, 1) scan_k(
    const float* __restrict__ whh, const float* __restrict__ whhp,
    const float* __restrict__ masks, const float* __restrict__ ginit,
    const float* __restrict__ bhh, const float* __restrict__ bhhp,
    const float* __restrict__ hxs, const float* __restrict__ hys,
    float* __restrict__ out)
{
    extern __shared__ unsigned sh[];
    unsigned* sW = sh + MB_U32;                 // 96 x 260
    unsigned* sA = sh + MB_U32 + 96 * SW_LD;    // 8 stages x 64 x 36

    unsigned smb;   // shared base address (mbarriers live at offset 0)
    asm("{ .reg .u64 t; cvta.to.shared.u64 t, %1; cvt.u32.u64 %0, t; }"
        : "=r"(smb) : "l"(sh));

    const int bx = blockIdx.x;
    const int p  = bx & 15;
    const int j0 = p * 32;
    const int m0 = ((bx >> 4) & 3) * 64;
    const int cell = bx >> 6;
    const int grp = bx >> 4;

    const float* W  = cell ? whhp : whh;
    const float* gi = cell ? g_gip : g_gi;
    const float* bh = cell ? bhhp : bhh;
    const float* hsrc = cell ? hys : hxs;
    float* outs = out + (cell ? (TNH + NH) : 0);
    float* hf   = out + (cell ? (2 * TNH + NH) : TNH);
    unsigned* bcnt = &g_bars[grp].cnt;
    unsigned* bgen = &g_bars[grp].gen;

    const int tid = threadIdx.x, lane = tid & 31, warp = tid >> 5;
    const int wm = warp & 1;
    const int wn = warp >> 1;

    // ---- mbarriers (256 noinc arrivals each per step) ----
    if (tid == 0) {
#pragma unroll
        for (int c = 0; c < 8; c++)
            asm volatile("mbarrier.init.shared.b64 [%0], %1;"
                         :: "r"(smb + c * 8), "r"(256u) : "memory");
    }

    // ---- preload weights into SMEM as fp16 ----
    for (int i = tid; i < 96 * 128; i += 256) {
        int rr = i >> 7;
        int f4 = i & 127;
        int g = rr >> 5, jj = rr & 31;
        float4 v = *reinterpret_cast<const float4*>(W + (size_t)(g * HH + j0 + jj) * HH + f4 * 4);
        sW[rr * SW_LD + f4 * 2]     = pack_h2(v.x, v.y);
        sW[rr * SW_LD + f4 * 2 + 1] = pack_h2(v.z, v.w);
    }

    // ---- init own slice of A(0) (global, half2 words) ----
    for (int idx = tid; idx < 64 * 16; idx += 256) {
        int row = idx >> 4, cp = idx & 15;
        int n = m0 + row, c = j0 + cp * 2;
        float mk = masks[n];
        float2 hv = *reinterpret_cast<const float2*>(hsrc + (size_t)n * HH + c);
        float a0 = hv.x * mk, a1 = hv.y * mk;
        if (cell) {
            float2 gv = *reinterpret_cast<const float2*>(ginit + (size_t)n * HH + c);
            a0 += gv.x * (1.f - mk);
            a1 += gv.y * (1.f - mk);
        }
        g_A16[cell][0][(size_t)n * 256 + (j0 >> 1) + cp] = pack_h2(a0, a1);
    }

    const int cb = j0 + wn * 8 + ((lane & 3) << 1);
    const float2 bn2 = *reinterpret_cast<const float2*>(bh + 2 * HH + cb);
    const unsigned sA_u32 = smb + ((MB_U32 + 96 * SW_LD) << 2);

    // ---- init barrier (publish A(0) slices; also orders mbarrier.init) ----
    {
        __syncthreads();
        if (tid == 0) {
            __threadfence();
            unsigned g0;
            asm volatile("ld.acquire.gpu.u32 %0, [%1];" : "=r"(g0) : "l"(bgen));
            unsigned v = atomicAdd(bcnt, 1u);
            if (v == GSIZE - 1) {
                *bcnt = 0u;
                asm volatile("st.release.gpu.u32 [%0], %1;" :: "l"(bgen), "r"(g0 + 1u));
            } else {
                unsigned cur;
                do { asm volatile("ld.acquire.gpu.u32 %0, [%1];" : "=r"(cur) : "l"(bgen)); }
                while (cur < g0 + 1u);
            }
        }
        __syncthreads();
    }

    // ---- register-carried state hq (fp32) ----
    float2 hq[4];
#pragma unroll
    for (int q = 0; q < 4; q++) {
        int n = m0 + wm * 32 + (q >> 1) * 16 + (lane >> 2) + (q & 1) * 8;
        float mk = masks[n];
        float2 hv = *reinterpret_cast<const float2*>(hsrc + (size_t)n * HH + cb);
        float a0 = hv.x * mk, a1 = hv.y * mk;
        if (cell) {
            float2 gv = *reinterpret_cast<const float2*>(ginit + (size_t)n * HH + cb);
            a0 += gv.x * (1.f - mk);
            a1 += gv.y * (1.f - mk);
        }
        hq[q] = make_float2(a0, a1);
    }

    // ---- initial operand prefetch ----
    float2 pir[4], piz[4], pin[4], pg[4];
    float pmask[4];
#pragma unroll
    for (int q = 0; q < 4; q++) {
        int n = m0 + wm * 32 + (q >> 1) * 16 + (lane >> 2) + (q & 1) * 8;
        size_t gb = (size_t)n * H3 + cb;
        pmask[q] = masks[NB + n];
        pir[q] = *reinterpret_cast<const float2*>(gi + gb);
        piz[q] = *reinterpret_cast<const float2*>(gi + gb + HH);
        pin[q] = *reinterpret_cast<const float2*>(gi + gb + 2 * HH);
        pg[q] = cell ? *reinterpret_cast<const float2*>(ginit + (size_t)(NB + n) * HH + cb)
                     : make_float2(0.f, 0.f);
    }

    for (int t = 0; t < TT; t++) {
        const int rb = t & 1;
        const unsigned* Ard = g_A16[cell][rb];
        unsigned*       Awr = g_A16[cell][rb ^ 1];
        const size_t trow = (size_t)t * NB;
        const unsigned* As = Ard + (size_t)m0 * 256;
        const unsigned par = (unsigned)(t & 1);

        // ---- issue ALL 8 chunks immediately (max MLP), mbarrier-tracked ----
#pragma unroll
        for (int c = 0; c < 8; c++) {
#pragma unroll
            for (int pp = 0; pp < 2; pp++) {
                int e = tid + pp * 256;
                int row = e >> 3;
                int c4 = (e & 7) << 2;
                unsigned d = sA_u32 + (((c * 64 + row) * SA_LD + c4) << 2);
                const unsigned* src = As + (size_t)row * 256 + c * 32 + c4;
                asm volatile("cp.async.cg.shared.global [%0], [%1], 16;" :: "r"(d), "l"(src));
            }
            asm volatile("cp.async.mbarrier.arrive.noinc.shared.b64 [%0];"
                         :: "r"(smb + c * 8) : "memory");
        }

        float acc[3][2][4];
#pragma unroll
        for (int g = 0; g < 3; g++)
#pragma unroll
            for (int mt = 0; mt < 2; mt++)
#pragma unroll
                for (int q = 0; q < 4; q++) acc[g][mt][q] = 0.f;

        for (int i = 0; i < 8; i++) {
            mbar_wait(smb + i * 8, par);
            const unsigned* sab = sA + i * 64 * SA_LD;
#pragma unroll
            for (int k16 = 0; k16 < 4; k16++) {
                const int ck = k16 * 8 + (lane & 3);
                unsigned af[2][4];
#pragma unroll
                for (int mt = 0; mt < 2; mt++) {
                    int r = wm * 32 + mt * 16 + (lane >> 2);
                    af[mt][0] = sab[r * SA_LD + ck];
                    af[mt][1] = sab[(r + 8) * SA_LD + ck];
                    af[mt][2] = sab[r * SA_LD + ck + 4];
                    af[mt][3] = sab[(r + 8) * SA_LD + ck + 4];
                }
                const int kg = i * 32 + k16 * 8 + (lane & 3);
#pragma unroll
                for (int g = 0; g < 3; g++) {
                    int bn = g * 32 + wn * 8 + (lane >> 2);
                    unsigned bf[2] = { sW[bn * SW_LD + kg], sW[bn * SW_LD + kg + 4] };
#pragma unroll
                    for (int mt = 0; mt < 2; mt++)
                        mma16h(acc[g][mt], af[mt], bf);
                }
            }
        }

        if (t < TT - 1) {
            // ---- gate math; h parked in acc[0], next-A (fp16) to global ----
#pragma unroll
            for (int mt = 0; mt < 2; mt++)
#pragma unroll
                for (int half = 0; half < 2; half++) {
                    int q = mt * 2 + half;
                    int n = m0 + wm * 32 + mt * 16 + (lane >> 2) + half * 8;
                    float mnx = pmask[q];
                    float rr0 = fsig(pir[q].x + acc[0][mt][half * 2]);
                    float rr1 = fsig(pir[q].y + acc[0][mt][half * 2 + 1]);
                    float zz0 = fsig(piz[q].x + acc[1][mt][half * 2]);
                    float zz1 = fsig(piz[q].y + acc[1][mt][half * 2 + 1]);
                    float nn0 = ftanh(pin[q].x + rr0 * (acc[2][mt][half * 2] + bn2.x));
                    float nn1 = ftanh(pin[q].y + rr1 * (acc[2][mt][half * 2 + 1] + bn2.y));
                    float h0 = (1.f - zz0) * nn0 + zz0 * hq[q].x;
                    float h1 = (1.f - zz1) * nn1 + zz1 * hq[q].y;
                    acc[0][mt][half * 2]     = h0;
                    acc[0][mt][half * 2 + 1] = h1;
                    float a0 = h0 * mnx + pg[q].x * (1.f - mnx);
                    float a1 = h1 * mnx + pg[q].y * (1.f - mnx);
                    Awr[(size_t)n * 256 + (cb >> 1)] = pack_h2(a0, a1);
                    hq[q] = make_float2(a0, a1);
                }

            // ---- arrive (non-blocking); syncs also provide stage WAR order ----
            __syncthreads();
            unsigned tgt = 0u;
            if (tid == 0) {
                __threadfence();
                unsigned g0;
                asm volatile("ld.acquire.gpu.u32 %0, [%1];" : "=r"(g0) : "l"(bgen));
                tgt = g0 + 1u;
                unsigned v = atomicAdd(bcnt, 1u);
                if (v == GSIZE - 1) {
                    *bcnt = 0u;
                    asm volatile("st.release.gpu.u32 [%0], %1;" :: "l"(bgen), "r"(tgt));
                }
            }

            // ---- shadow work: outs stores + next-step prefetch ----
#pragma unroll
            for (int mt = 0; mt < 2; mt++)
#pragma unroll
                for (int half = 0; half < 2; half++) {
                    int n = m0 + wm * 32 + mt * 16 + (lane >> 2) + half * 8;
                    *reinterpret_cast<float2*>(outs + (trow + n) * HH + cb) =
                        make_float2(acc[0][mt][half * 2], acc[0][mt][half * 2 + 1]);
                }
            const size_t trow1 = trow + NB;
            const bool hasnext2 = (t + 2 < TT);
#pragma unroll
            for (int q = 0; q < 4; q++) {
                int n = m0 + wm * 32 + (q >> 1) * 16 + (lane >> 2) + (q & 1) * 8;
                size_t gb = (trow1 + n) * (size_t)H3 + cb;
                pmask[q] = hasnext2 ? masks[trow1 + NB + n] : 0.f;
                pir[q] = *reinterpret_cast<const float2*>(gi + gb);
                piz[q] = *reinterpret_cast<const float2*>(gi + gb + HH);
                pin[q] = *reinterpret_cast<const float2*>(gi + gb + 2 * HH);
                pg[q] = (cell && hasnext2)
                    ? *reinterpret_cast<const float2*>(
                          ginit + (size_t)(trow1 + NB + n) * HH + cb)
                    : make_float2(0.f, 0.f);
            }

            // ---- wait ----
            if (tid == 0) {
                unsigned cur;
                do { asm volatile("ld.acquire.gpu.u32 %0, [%1];" : "=r"(cur) : "l"(bgen)); }
                while (cur < tgt);
            }
            __syncthreads();
        } else {
            // ---- final step ----
#pragma unroll
            for (int mt = 0; mt < 2; mt++)
#pragma unroll
                for (int half = 0; half < 2; half++) {
                    int q = mt * 2 + half;
                    int n = m0 + wm * 32 + mt * 16 + (lane >> 2) + half * 8;
                    size_t mrow = trow + n;
                    float rr0 = fsig(pir[q].x + acc[0][mt][half * 2]);
                    float rr1 = fsig(pir[q].y + acc[0][mt][half * 2 + 1]);
                    float zz0 = fsig(piz[q].x + acc[1][mt][half * 2]);
                    float zz1 = fsig(piz[q].y + acc[1][mt][half * 2 + 1]);
                    float nn0 = ftanh(pin[q].x + rr0 * (acc[2][mt][half * 2] + bn2.x));
                    float nn1 = ftanh(pin[q].y + rr1 * (acc[2][mt][half * 2 + 1] + bn2.y));
                    float h0 = (1.f - zz0) * nn0 + zz0 * hq[q].x;
                    float h1 = (1.f - zz1) * nn1 + zz1 * hq[q].y;
                    *reinterpret_cast<float2*>(outs + mrow * HH + cb) = make_float2(h0, h1);
                    *reinterpret_cast<float2*>(hf + (size_t)n * HH + cb) = make_float2(h0, h1);
                }
        }
    }
}

extern "C" void kernel_launch(void* const* d_in, const int* in_sizes, int n_in,
                              void* d_out, int out_size)
{
    const float* x     = (const float*)d_in[0];
    const float* hxs   = (const float*)d_in[1];
    const float* hys   = (const float*)d_in[2];
    const float* ginit = (const float*)d_in[3];
    const float* masks = (const float*)d_in[4];
    const float* pah   = (const float*)d_in[5];
    const float* wih   = (const float*)d_in[6];
    const float* whh   = (const float*)d_in[7];
    const float* bih   = (const float*)d_in[8];
    const float* bhh   = (const float*)d_in[9];
    const float* wihp  = (const float*)d_in[10];
    const float* whhp  = (const float*)d_in[11];
    const float* bihp  = (const float*)d_in[12];
    const float* bhhp  = (const float*)d_in[13];
    float* out = (float*)d_out;

    gi_gemm_k<<<dim3(12, 256), 256>>>(x, wih, wihp, pah, masks, bih, bihp, bhh, bhhp);

    cudaFuncSetAttribute(scan_k, cudaFuncAttributeMaxDynamicSharedMemorySize, SMEM_SCAN);
    scan_k<<<NCTA, 256, SMEM_SCAN>>>(whh, whhp, masks, ginit, bhh, bhhp, hxs, hys, out);
}

// round 16
// speedup vs baseline: 1.7273x; 1.1243x over previous
#include <cuda_runtime.h>
#include <cuda_fp16.h>
#include <math.h>

#define TT 128
#define NB 256
#define EE 512
#define AD 8
#define HH 512
#define H3 1536
#define TN (TT*NB)
#define TNH ((size_t)TN*HH)
#define NH (NB*HH)
#define NCTA 128
#define NGROUP 8
#define GSIZE 16

// Scratch (no cudaMalloc allowed)
__device__ float g_gi [(size_t)TN * H3];
__device__ float g_gip[(size_t)TN * H3];
__device__ unsigned g_A16[2][2][NH/2];     // masked hidden state as half2 words
struct __align__(128) Bar { unsigned cnt; unsigned gen; unsigned pad[30]; };
__device__ Bar g_bars[NGROUP];

__device__ __forceinline__ unsigned pack_h2(float a, float b) {
    __half2 h = __floats2half2_rn(a, b);
    return *reinterpret_cast<unsigned*>(&h);
}

// fp16 m16n8k16, fp32 accumulate
__device__ __forceinline__ void mma16h(float* c, const unsigned* a, const unsigned* b) {
    asm volatile(
        "mma.sync.aligned.m16n8k16.row.col.f32.f16.f16.f32 "
        "{%0,%1,%2,%3},{%4,%5,%6,%7},{%8,%9},{%0,%1,%2,%3};"
        : "+f"(c[0]), "+f"(c[1]), "+f"(c[2]), "+f"(c[3])
        : "r"(a[0]), "r"(a[1]), "r"(a[2]), "r"(a[3]), "r"(b[0]), "r"(b[1]));
}

__device__ __forceinline__ float fsig(float x) { return 1.f / (1.f + __expf(-x)); }
__device__ __forceinline__ float ftanh(float x) { return 1.f - 2.f / (__expf(2.f * x) + 1.f); }

__device__ __forceinline__ void mbar_wait(unsigned mb, unsigned parity) {
    unsigned done;
    asm volatile(
        "{\n\t.reg .pred p;\n\t"
        "mbarrier.try_wait.parity.acquire.cta.shared::cta.b64 p, [%1], %2;\n\t"
        "selp.b32 %0, 1, 0, p;\n\t}"
        : "=r"(done) : "r"(mb), "r"(parity) : "memory");
    if (!done) {
        asm volatile(
            "{\n\t.reg .pred P1;\n\t"
            "W_%=:\n\t"
            "mbarrier.try_wait.parity.acquire.cta.shared::cta.b64 P1, [%0], %1, 0x989680;\n\t"
            "@P1 bra.uni D_%=;\n\t"
            "bra.uni W_%=;\n\t"
            "D_%=:\n\t}"
            :: "r"(mb), "r"(parity) : "memory");
    }
}

// ===========================================================================
// GI GEMM, fp16 operands / fp32 accumulate. 2 CTAs/SM (reg cap 128) so the
// sync-pipelined k-loop latency is hidden by cross-CTA interleaving.
// ===========================================================================
__global__ void __launch_bounds__(256, 2) gi_gemm_k(
    const float* __restrict__ x,
    const float* __restrict__ wih,  const float* __restrict__ wihp,
    const float* __restrict__ pah,  const float* __restrict__ masks,
    const float* __restrict__ bih,  const float* __restrict__ bihp,
    const float* __restrict__ bhh,  const float* __restrict__ bhhp)
{
    constexpr int SAH = 20;
    __shared__ unsigned sA[2][128 * SAH];
    __shared__ unsigned sB[2][128 * SAH];

    const int m0 = blockIdx.y * 128;
    const int n0 = blockIdx.x * 128;
    const float* Bg = wih + (size_t)n0 * 520;

    const int tid = threadIdx.x, lane = tid & 31, warp = tid >> 5;
    const int wm = warp & 1, wn = warp >> 1;

    float acc[4][4][4];
#pragma unroll
    for (int i = 0; i < 4; i++)
#pragma unroll
        for (int j = 0; j < 4; j++)
#pragma unroll
            for (int q = 0; q < 4; q++) acc[i][j][q] = 0.f;

    unsigned ra[4][2], rb[4][2];

    auto GL = [&](int kc) {
#pragma unroll
        for (int i = 0; i < 4; i++) {
            int s = tid + i * 256; int r = s >> 3; int c4 = (s & 7) << 2;
            float4 v = *reinterpret_cast<const float4*>(x + (size_t)(m0 + r) * EE + kc * 32 + c4);
            ra[i][0] = pack_h2(v.x, v.y); ra[i][1] = pack_h2(v.z, v.w);
            float4 w = *reinterpret_cast<const float4*>(Bg + (size_t)r * 520 + kc * 32 + c4);
            rb[i][0] = pack_h2(w.x, w.y); rb[i][1] = pack_h2(w.z, w.w);
        }
    };
    auto SS = [&](int buf) {
#pragma unroll
        for (int i = 0; i < 4; i++) {
            int s = tid + i * 256; int r = s >> 3; int c2 = (s & 7) << 1;
            sA[buf][r * SAH + c2]     = ra[i][0];
            sA[buf][r * SAH + c2 + 1] = ra[i][1];
            sB[buf][r * SAH + c2]     = rb[i][0];
            sB[buf][r * SAH + c2 + 1] = rb[i][1];
        }
    };
    auto COMP = [&](int buf) {
#pragma unroll
        for (int k16 = 0; k16 < 2; k16++) {
            const int ck = k16 * 8 + (lane & 3);
            unsigned af[4][4]; unsigned bf[4][2];
#pragma unroll
            for (int mt = 0; mt < 4; mt++) {
                int r = wm * 64 + mt * 16 + (lane >> 2);
                af[mt][0] = sA[buf][r * SAH + ck];
                af[mt][1] = sA[buf][(r + 8) * SAH + ck];
                af[mt][2] = sA[buf][r * SAH + ck + 4];
                af[mt][3] = sA[buf][(r + 8) * SAH + ck + 4];
            }
#pragma unroll
            for (int nt = 0; nt < 4; nt++) {
                int n = wn * 32 + nt * 8 + (lane >> 2);
                bf[nt][0] = sB[buf][n * SAH + ck];
                bf[nt][1] = sB[buf][n * SAH + ck + 4];
            }
#pragma unroll
            for (int mt = 0; mt < 4; mt++)
#pragma unroll
                for (int nt = 0; nt < 4; nt++)
                    mma16h(acc[mt][nt], af[mt], bf[nt]);
        }
    };

    GL(0); SS(0); __syncthreads();
    constexpr int NKC = EE / 32;
    for (int kc = 0; kc < NKC; kc++) {
        if (kc + 1 < NKC) GL(kc + 1);
        COMP(kc & 1);
        if (kc + 1 < NKC) SS((kc + 1) & 1);
        __syncthreads();
    }

    {
        int r = tid >> 1, hi = tid & 1;
        float mk = masks[m0 + r];
        float4 v = *reinterpret_cast<const float4*>(pah + (size_t)(m0 + r) * AD + hi * 4);
        sA[0][r * SAH + hi * 2]     = pack_h2(v.x * mk, v.y * mk);
        sA[0][r * SAH + hi * 2 + 1] = pack_h2(v.z * mk, v.w * mk);
        sA[0][r * SAH + 4 + hi * 2]     = 0u;
        sA[0][r * SAH + 4 + hi * 2 + 1] = 0u;
        float4 w = *reinterpret_cast<const float4*>(wih + (size_t)(n0 + r) * 520 + 512 + hi * 4);
        sB[0][r * SAH + hi * 2]     = pack_h2(w.x, w.y);
        sB[0][r * SAH + hi * 2 + 1] = pack_h2(w.z, w.w);
        sB[0][r * SAH + 4 + hi * 2]     = 0u;
        sB[0][r * SAH + 4 + hi * 2 + 1] = 0u;
        float4 u = *reinterpret_cast<const float4*>(wihp + (size_t)(n0 + r) * AD + hi * 4);
        sB[1][r * SAH + hi * 2]     = pack_h2(u.x, u.y);
        sB[1][r * SAH + hi * 2 + 1] = pack_h2(u.z, u.w);
        sB[1][r * SAH + 4 + hi * 2]     = 0u;
        sB[1][r * SAH + 4 + hi * 2 + 1] = 0u;
    }
    __syncthreads();
    {
        const int ck = (lane & 3);
        unsigned af2[4][4], b0f[4][2], b1f[4][2];
#pragma unroll
        for (int mt = 0; mt < 4; mt++) {
            int r = wm * 64 + mt * 16 + (lane >> 2);
            af2[mt][0] = sA[0][r * SAH + ck];
            af2[mt][1] = sA[0][(r + 8) * SAH + ck];
            af2[mt][2] = sA[0][r * SAH + ck + 4];
            af2[mt][3] = sA[0][(r + 8) * SAH + ck + 4];
        }
#pragma unroll
        for (int nt = 0; nt < 4; nt++) {
            int n = wn * 32 + nt * 8 + (lane >> 2);
            b0f[nt][0] = sB[0][n * SAH + ck]; b0f[nt][1] = sB[0][n * SAH + ck + 4];
            b1f[nt][0] = sB[1][n * SAH + ck]; b1f[nt][1] = sB[1][n * SAH + ck + 4];
        }
#pragma unroll
        for (int mt = 0; mt < 4; mt++)
#pragma unroll
            for (int nt = 0; nt < 4; nt++) {
                mma16h(acc[mt][nt], af2[mt], b0f[nt]);
                float acc2l[4] = {0.f, 0.f, 0.f, 0.f};
                mma16h(acc2l, af2[mt], b1f[nt]);

                int r = m0 + wm * 64 + mt * 16 + (lane >> 2);
                int c = n0 + wn * 32 + nt * 8 + ((lane & 3) << 1);
                float hb0 = (c < 1024) ? bhh[c] : 0.f;
                float hb1 = (c < 1024) ? bhh[c + 1] : 0.f;
                float b0 = bih[c] + hb0, b1 = bih[c + 1] + hb1;
                *reinterpret_cast<float2*>(&g_gi[(size_t)r * H3 + c]) =
                    make_float2(acc[mt][nt][0] + b0, acc[mt][nt][1] + b1);
                *reinterpret_cast<float2*>(&g_gi[(size_t)(r + 8) * H3 + c]) =
                    make_float2(acc[mt][nt][2] + b0, acc[mt][nt][3] + b1);
                float pb0 = (c < 1024) ? bhhp[c] : 0.f;
                float pb1 = (c < 1024) ? bhhp[c + 1] : 0.f;
                float p0 = bihp[c] + pb0, p1 = bihp[c + 1] + pb1;
                *reinterpret_cast<float2*>(&g_gip[(size_t)r * H3 + c]) =
                    make_float2(acc2l[0] + p0, acc2l[1] + p1);
                *reinterpret_cast<float2*>(&g_gip[(size_t)(r + 8) * H3 + c]) =
                    make_float2(acc2l[2] + p0, acc2l[3] + p1);
            }
    }
}

// ===========================================================================
// Persistent scan (R15 winner, unchanged): FP16 K=16 MMA, 8 fully-prefetched
// stages, mbarrier .noinc tracked cp.async. 128 CTAs x 256 threads.
// ===========================================================================
#define SW_LD 260   // u32 per W row
#define SA_LD 36    // u32 per A chunk row
#define MB_U32 16                           // 8 mbarriers (64 B)
#define SMEM_SCAN ((MB_U32 + 96*SW_LD + 8*64*SA_LD) * 4)

__global__ void __launch_bounds__(256, 1) scan_k(
    const float* __restrict__ whh, const float* __restrict__ whhp,
    const float* __restrict__ masks, const float* __restrict__ ginit,
    const float* __restrict__ bhh, const float* __restrict__ bhhp,
    const float* __restrict__ hxs, const float* __restrict__ hys,
    float* __restrict__ out)
{
    extern __shared__ unsigned sh[];
    unsigned* sW = sh + MB_U32;                 // 96 x 260
    unsigned* sA = sh + MB_U32 + 96 * SW_LD;    // 8 stages x 64 x 36

    unsigned smb;   // shared base address (mbarriers live at offset 0)
    asm("{ .reg .u64 t; cvta.to.shared.u64 t, %1; cvt.u32.u64 %0, t; }"
        : "=r"(smb) : "l"(sh));

    const int bx = blockIdx.x;
    const int p  = bx & 15;
    const int j0 = p * 32;
    const int m0 = ((bx >> 4) & 3) * 64;
    const int cell = bx >> 6;
    const int grp = bx >> 4;

    const float* W  = cell ? whhp : whh;
    const float* gi = cell ? g_gip : g_gi;
    const float* bh = cell ? bhhp : bhh;
    const float* hsrc = cell ? hys : hxs;
    float* outs = out + (cell ? (TNH + NH) : 0);
    float* hf   = out + (cell ? (2 * TNH + NH) : TNH);
    unsigned* bcnt = &g_bars[grp].cnt;
    unsigned* bgen = &g_bars[grp].gen;

    const int tid = threadIdx.x, lane = tid & 31, warp = tid >> 5;
    const int wm = warp & 1;
    const int wn = warp >> 1;

    // ---- mbarriers (256 noinc arrivals each per step) ----
    if (tid == 0) {
#pragma unroll
        for (int c = 0; c < 8; c++)
            asm volatile("mbarrier.init.shared.b64 [%0], %1;"
                         :: "r"(smb + c * 8), "r"(256u) : "memory");
    }

    // ---- preload weights into SMEM as fp16 ----
    for (int i = tid; i < 96 * 128; i += 256) {
        int rr = i >> 7;
        int f4 = i & 127;
        int g = rr >> 5, jj = rr & 31;
        float4 v = *reinterpret_cast<const float4*>(W + (size_t)(g * HH + j0 + jj) * HH + f4 * 4);
        sW[rr * SW_LD + f4 * 2]     = pack_h2(v.x, v.y);
        sW[rr * SW_LD + f4 * 2 + 1] = pack_h2(v.z, v.w);
    }

    // ---- init own slice of A(0) (global, half2 words) ----
    for (int idx = tid; idx < 64 * 16; idx += 256) {
        int row = idx >> 4, cp = idx & 15;
        int n = m0 + row, c = j0 + cp * 2;
        float mk = masks[n];
        float2 hv = *reinterpret_cast<const float2*>(hsrc + (size_t)n * HH + c);
        float a0 = hv.x * mk, a1 = hv.y * mk;
        if (cell) {
            float2 gv = *reinterpret_cast<const float2*>(ginit + (size_t)n * HH + c);
            a0 += gv.x * (1.f - mk);
            a1 += gv.y * (1.f - mk);
        }
        g_A16[cell][0][(size_t)n * 256 + (j0 >> 1) + cp] = pack_h2(a0, a1);
    }

    const int cb = j0 + wn * 8 + ((lane & 3) << 1);
    const float2 bn2 = *reinterpret_cast<const float2*>(bh + 2 * HH + cb);
    const unsigned sA_u32 = smb + ((MB_U32 + 96 * SW_LD) << 2);

    // ---- init barrier (publish A(0) slices; also orders mbarrier.init) ----
    {
        __syncthreads();
        if (tid == 0) {
            __threadfence();
            unsigned g0;
            asm volatile("ld.acquire.gpu.u32 %0, [%1];" : "=r"(g0) : "l"(bgen));
            unsigned v = atomicAdd(bcnt, 1u);
            if (v == GSIZE - 1) {
                *bcnt = 0u;
                asm volatile("st.release.gpu.u32 [%0], %1;" :: "l"(bgen), "r"(g0 + 1u));
            } else {
                unsigned cur;
                do { asm volatile("ld.acquire.gpu.u32 %0, [%1];" : "=r"(cur) : "l"(bgen)); }
                while (cur < g0 + 1u);
            }
        }
        __syncthreads();
    }

    // ---- register-carried state hq (fp32) ----
    float2 hq[4];
#pragma unroll
    for (int q = 0; q < 4; q++) {
        int n = m0 + wm * 32 + (q >> 1) * 16 + (lane >> 2) + (q & 1) * 8;
        float mk = masks[n];
        float2 hv = *reinterpret_cast<const float2*>(hsrc + (size_t)n * HH + cb);
        float a0 = hv.x * mk, a1 = hv.y * mk;
        if (cell) {
            float2 gv = *reinterpret_cast<const float2*>(ginit + (size_t)n * HH + cb);
            a0 += gv.x * (1.f - mk);
            a1 += gv.y * (1.f - mk);
        }
        hq[q] = make_float2(a0, a1);
    }

    // ---- initial operand prefetch ----
    float2 pir[4], piz[4], pin[4], pg[4];
    float pmask[4];
#pragma unroll
    for (int q = 0; q < 4; q++) {
        int n = m0 + wm * 32 + (q >> 1) * 16 + (lane >> 2) + (q & 1) * 8;
        size_t gb = (size_t)n * H3 + cb;
        pmask[q] = masks[NB + n];
        pir[q] = *reinterpret_cast<const float2*>(gi + gb);
        piz[q] = *reinterpret_cast<const float2*>(gi + gb + HH);
        pin[q] = *reinterpret_cast<const float2*>(gi + gb + 2 * HH);
        pg[q] = cell ? *reinterpret_cast<const float2*>(ginit + (size_t)(NB + n) * HH + cb)
                     : make_float2(0.f, 0.f);
    }

    for (int t = 0; t < TT; t++) {
        const int rb = t & 1;
        const unsigned* Ard = g_A16[cell][rb];
        unsigned*       Awr = g_A16[cell][rb ^ 1];
        const size_t trow = (size_t)t * NB;
        const unsigned* As = Ard + (size_t)m0 * 256;
        const unsigned par = (unsigned)(t & 1);

        // ---- issue ALL 8 chunks immediately (max MLP), mbarrier-tracked ----
#pragma unroll
        for (int c = 0; c < 8; c++) {
#pragma unroll
            for (int pp = 0; pp < 2; pp++) {
                int e = tid + pp * 256;
                int row = e >> 3;
                int c4 = (e & 7) << 2;
                unsigned d = sA_u32 + (((c * 64 + row) * SA_LD + c4) << 2);
                const unsigned* src = As + (size_t)row * 256 + c * 32 + c4;
                asm volatile("cp.async.cg.shared.global [%0], [%1], 16;" :: "r"(d), "l"(src));
            }
            asm volatile("cp.async.mbarrier.arrive.noinc.shared.b64 [%0];"
                         :: "r"(smb + c * 8) : "memory");
        }

        float acc[3][2][4];
#pragma unroll
        for (int g = 0; g < 3; g++)
#pragma unroll
            for (int mt = 0; mt < 2; mt++)
#pragma unroll
                for (int q = 0; q < 4; q++) acc[g][mt][q] = 0.f;

        for (int i = 0; i < 8; i++) {
            mbar_wait(smb + i * 8, par);
            const unsigned* sab = sA + i * 64 * SA_LD;
#pragma unroll
            for (int k16 = 0; k16 < 4; k16++) {
                const int ck = k16 * 8 + (lane & 3);
                unsigned af[2][4];
#pragma unroll
                for (int mt = 0; mt < 2; mt++) {
                    int r = wm * 32 + mt * 16 + (lane >> 2);
                    af[mt][0] = sab[r * SA_LD + ck];
                    af[mt][1] = sab[(r + 8) * SA_LD + ck];
                    af[mt][2] = sab[r * SA_LD + ck + 4];
                    af[mt][3] = sab[(r + 8) * SA_LD + ck + 4];
                }
                const int kg = i * 32 + k16 * 8 + (lane & 3);
#pragma unroll
                for (int g = 0; g < 3; g++) {
                    int bn = g * 32 + wn * 8 + (lane >> 2);
                    unsigned bf[2] = { sW[bn * SW_LD + kg], sW[bn * SW_LD + kg + 4] };
#pragma unroll
                    for (int mt = 0; mt < 2; mt++)
                        mma16h(acc[g][mt], af[mt], bf);
                }
            }
        }

        if (t < TT - 1) {
            // ---- gate math; h parked in acc[0], next-A (fp16) to global ----
#pragma unroll
            for (int mt = 0; mt < 2; mt++)
#pragma unroll
                for (int half = 0; half < 2; half++) {
                    int q = mt * 2 + half;
                    int n = m0 + wm * 32 + mt * 16 + (lane >> 2) + half * 8;
                    float mnx = pmask[q];
                    float rr0 = fsig(pir[q].x + acc[0][mt][half * 2]);
                    float rr1 = fsig(pir[q].y + acc[0][mt][half * 2 + 1]);
                    float zz0 = fsig(piz[q].x + acc[1][mt][half * 2]);
                    float zz1 = fsig(piz[q].y + acc[1][mt][half * 2 + 1]);
                    float nn0 = ftanh(pin[q].x + rr0 * (acc[2][mt][half * 2] + bn2.x));
                    float nn1 = ftanh(pin[q].y + rr1 * (acc[2][mt][half * 2 + 1] + bn2.y));
                    float h0 = (1.f - zz0) * nn0 + zz0 * hq[q].x;
                    float h1 = (1.f - zz1) * nn1 + zz1 * hq[q].y;
                    acc[0][mt][half * 2]     = h0;
                    acc[0][mt][half * 2 + 1] = h1;
                    float a0 = h0 * mnx + pg[q].x * (1.f - mnx);
                    float a1 = h1 * mnx + pg[q].y * (1.f - mnx);
                    Awr[(size_t)n * 256 + (cb >> 1)] = pack_h2(a0, a1);
                    hq[q] = make_float2(a0, a1);
                }

            // ---- arrive (non-blocking); syncs also provide stage WAR order ----
            __syncthreads();
            unsigned tgt = 0u;
            if (tid == 0) {
                __threadfence();
                unsigned g0;
                asm volatile("ld.acquire.gpu.u32 %0, [%1];" : "=r"(g0) : "l"(bgen));
                tgt = g0 + 1u;
                unsigned v = atomicAdd(bcnt, 1u);
                if (v == GSIZE - 1) {
                    *bcnt = 0u;
                    asm volatile("st.release.gpu.u32 [%0], %1;" :: "l"(bgen), "r"(tgt));
                }
            }

            // ---- shadow work: outs stores + next-step prefetch ----
#pragma unroll
            for (int mt = 0; mt < 2; mt++)
#pragma unroll
                for (int half = 0; half < 2; half++) {
                    int n = m0 + wm * 32 + mt * 16 + (lane >> 2) + half * 8;
                    *reinterpret_cast<float2*>(outs + (trow + n) * HH + cb) =
                        make_float2(acc[0][mt][half * 2], acc[0][mt][half * 2 + 1]);
                }
            const size_t trow1 = trow + NB;
            const bool hasnext2 = (t + 2 < TT);
#pragma unroll
            for (int q = 0; q < 4; q++) {
                int n = m0 + wm * 32 + (q >> 1) * 16 + (lane >> 2) + (q & 1) * 8;
                size_t gb = (trow1 + n) * (size_t)H3 + cb;
                pmask[q] = hasnext2 ? masks[trow1 + NB + n] : 0.f;
                pir[q] = *reinterpret_cast<const float2*>(gi + gb);
                piz[q] = *reinterpret_cast<const float2*>(gi + gb + HH);
                pin[q] = *reinterpret_cast<const float2*>(gi + gb + 2 * HH);
                pg[q] = (cell && hasnext2)
                    ? *reinterpret_cast<const float2*>(
                          ginit + (size_t)(trow1 + NB + n) * HH + cb)
                    : make_float2(0.f, 0.f);
            }

            // ---- wait ----
            if (tid == 0) {
                unsigned cur;
                do { asm volatile("ld.acquire.gpu.u32 %0, [%1];" : "=r"(cur) : "l"(bgen)); }
                while (cur < tgt);
            }
            __syncthreads();
        } else {
            // ---- final step ----
#pragma unroll
            for (int mt = 0; mt < 2; mt++)
#pragma unroll
                for (int half = 0; half < 2; half++) {
                    int q = mt * 2 + half;
                    int n = m0 + wm * 32 + mt * 16 + (lane >> 2) + half * 8;
                    size_t mrow = trow + n;
                    float rr0 = fsig(pir[q].x + acc[0][mt][half * 2]);
                    float rr1 = fsig(pir[q].y + acc[0][mt][half * 2 + 1]);
                    float zz0 = fsig(piz[q].x + acc[1][mt][half * 2]);
                    float zz1 = fsig(piz[q].y + acc[1][mt][half * 2 + 1]);
                    float nn0 = ftanh(pin[q].x + rr0 * (acc[2][mt][half * 2] + bn2.x));
                    float nn1 = ftanh(pin[q].y + rr1 * (acc[2][mt][half * 2 + 1] + bn2.y));
                    float h0 = (1.f - zz0) * nn0 + zz0 * hq[q].x;
                    float h1 = (1.f - zz1) * nn1 + zz1 * hq[q].y;
                    *reinterpret_cast<float2*>(outs + mrow * HH + cb) = make_float2(h0, h1);
                    *reinterpret_cast<float2*>(hf + (size_t)n * HH + cb) = make_float2(h0, h1);
                }
        }
    }
}

extern "C" void kernel_launch(void* const* d_in, const int* in_sizes, int n_in,
                              void* d_out, int out_size)
{
    const float* x     = (const float*)d_in[0];
    const float* hxs   = (const float*)d_in[1];
    const float* hys   = (const float*)d_in[2];
    const float* ginit = (const float*)d_in[3];
    const float* masks = (const float*)d_in[4];
    const float* pah   = (const float*)d_in[5];
    const float* wih   = (const float*)d_in[6];
    const float* whh   = (const float*)d_in[7];
    const float* bih   = (const float*)d_in[8];
    const float* bhh   = (const float*)d_in[9];
    const float* wihp  = (const float*)d_in[10];
    const float* whhp  = (const float*)d_in[11];
    const float* bihp  = (const float*)d_in[12];
    const float* bhhp  = (const float*)d_in[13];
    float* out = (float*)d_out;

    gi_gemm_k<<<dim3(12, 256), 256>>>(x, wih, wihp, pah, masks, bih, bihp, bhh, bhhp);

    cudaFuncSetAttribute(scan_k, cudaFuncAttributeMaxDynamicSharedMemorySize, SMEM_SCAN);
    scan_k<<<NCTA, 256, SMEM_SCAN>>>(whh, whhp, masks, ginit, bhh, bhhp, hxs, hys, out);
}

// round 17
// speedup vs baseline: 1.7433x; 1.0093x over previous
#include <cuda_runtime.h>
#include <cuda_fp16.h>
#include <math.h>

#define TT 128
#define NB 256
#define EE 512
#define AD 8
#define HH 512
#define H3 1536
#define TN (TT*NB)
#define TNH ((size_t)TN*HH)
#define NH (NB*HH)
#define NCTA 128
#define NGROUP 8
#define GSIZE 16

// Scratch (no cudaMalloc allowed)
__device__ unsigned g_gi16 [(size_t)TN * H3 / 2];   // input-side gates, cell 1, half2
__device__ unsigned g_gip16[(size_t)TN * H3 / 2];   // input-side gates, cell 2, half2
__device__ unsigned g_A16[2][2][NH/2];              // masked hidden state as half2 words
struct __align__(128) Bar { unsigned cnt; unsigned gen; unsigned pad[30]; };
__device__ Bar g_bars[NGROUP];

__device__ __forceinline__ unsigned pack_h2(float a, float b) {
    __half2 h = __floats2half2_rn(a, b);
    return *reinterpret_cast<unsigned*>(&h);
}
__device__ __forceinline__ float2 h2f2(unsigned u) {
    __half2 h = *reinterpret_cast<__half2*>(&u);
    return __half22float2(h);
}

// fp16 m16n8k16, fp32 accumulate
__device__ __forceinline__ void mma16h(float* c, const unsigned* a, const unsigned* b) {
    asm volatile(
        "mma.sync.aligned.m16n8k16.row.col.f32.f16.f16.f32 "
        "{%0,%1,%2,%3},{%4,%5,%6,%7},{%8,%9},{%0,%1,%2,%3};"
        : "+f"(c[0]), "+f"(c[1]), "+f"(c[2]), "+f"(c[3])
        : "r"(a[0]), "r"(a[1]), "r"(a[2]), "r"(a[3]), "r"(b[0]), "r"(b[1]));
}

__device__ __forceinline__ float fsig(float x) { return 1.f / (1.f + __expf(-x)); }
__device__ __forceinline__ float ftanh(float x) { return 1.f - 2.f / (__expf(2.f * x) + 1.f); }

__device__ __forceinline__ void mbar_wait(unsigned mb, unsigned parity) {
    unsigned done;
    asm volatile(
        "{\n\t.reg .pred p;\n\t"
        "mbarrier.try_wait.parity.acquire.cta.shared::cta.b64 p, [%1], %2;\n\t"
        "selp.b32 %0, 1, 0, p;\n\t}"
        : "=r"(done) : "r"(mb), "r"(parity) : "memory");
    if (!done) {
        asm volatile(
            "{\n\t.reg .pred P1;\n\t"
            "W_%=:\n\t"
            "mbarrier.try_wait.parity.acquire.cta.shared::cta.b64 P1, [%0], %1, 0x989680;\n\t"
            "@P1 bra.uni D_%=;\n\t"
            "bra.uni W_%=;\n\t"
            "D_%=:\n\t}"
            :: "r"(mb), "r"(parity) : "memory");
    }
}

// ===========================================================================
// GI GEMM, fp16 operands / fp32 accumulate, fp16 packed output. 2 CTAs/SM.
// ===========================================================================
__global__ void __launch_bounds__(256, 2) gi_gemm_k(
    const float* __restrict__ x,
    const float* __restrict__ wih,  const float* __restrict__ wihp,
    const float* __restrict__ pah,  const float* __restrict__ masks,
    const float* __restrict__ bih,  const float* __restrict__ bihp,
    const float* __restrict__ bhh,  const float* __restrict__ bhhp)
{
    constexpr int SAH = 20;
    __shared__ unsigned sA[2][128 * SAH];
    __shared__ unsigned sB[2][128 * SAH];

    const int m0 = blockIdx.y * 128;
    const int n0 = blockIdx.x * 128;
    const float* Bg = wih + (size_t)n0 * 520;

    const int tid = threadIdx.x, lane = tid & 31, warp = tid >> 5;
    const int wm = warp & 1, wn = warp >> 1;

    float acc[4][4][4];
#pragma unroll
    for (int i = 0; i < 4; i++)
#pragma unroll
        for (int j = 0; j < 4; j++)
#pragma unroll
            for (int q = 0; q < 4; q++) acc[i][j][q] = 0.f;

    unsigned ra[4][2], rb[4][2];

    auto GL = [&](int kc) {
#pragma unroll
        for (int i = 0; i < 4; i++) {
            int s = tid + i * 256; int r = s >> 3; int c4 = (s & 7) << 2;
            float4 v = *reinterpret_cast<const float4*>(x + (size_t)(m0 + r) * EE + kc * 32 + c4);
            ra[i][0] = pack_h2(v.x, v.y); ra[i][1] = pack_h2(v.z, v.w);
            float4 w = *reinterpret_cast<const float4*>(Bg + (size_t)r * 520 + kc * 32 + c4);
            rb[i][0] = pack_h2(w.x, w.y); rb[i][1] = pack_h2(w.z, w.w);
        }
    };
    auto SS = [&](int buf) {
#pragma unroll
        for (int i = 0; i < 4; i++) {
            int s = tid + i * 256; int r = s >> 3; int c2 = (s & 7) << 1;
            sA[buf][r * SAH + c2]     = ra[i][0];
            sA[buf][r * SAH + c2 + 1] = ra[i][1];
            sB[buf][r * SAH + c2]     = rb[i][0];
            sB[buf][r * SAH + c2 + 1] = rb[i][1];
        }
    };
    auto COMP = [&](int buf) {
#pragma unroll
        for (int k16 = 0; k16 < 2; k16++) {
            const int ck = k16 * 8 + (lane & 3);
            unsigned af[4][4]; unsigned bf[4][2];
#pragma unroll
            for (int mt = 0; mt < 4; mt++) {
                int r = wm * 64 + mt * 16 + (lane >> 2);
                af[mt][0] = sA[buf][r * SAH + ck];
                af[mt][1] = sA[buf][(r + 8) * SAH + ck];
                af[mt][2] = sA[buf][r * SAH + ck + 4];
                af[mt][3] = sA[buf][(r + 8) * SAH + ck + 4];
            }
#pragma unroll
            for (int nt = 0; nt < 4; nt++) {
                int n = wn * 32 + nt * 8 + (lane >> 2);
                bf[nt][0] = sB[buf][n * SAH + ck];
                bf[nt][1] = sB[buf][n * SAH + ck + 4];
            }
#pragma unroll
            for (int mt = 0; mt < 4; mt++)
#pragma unroll
                for (int nt = 0; nt < 4; nt++)
                    mma16h(acc[mt][nt], af[mt], bf[nt]);
        }
    };

    GL(0); SS(0); __syncthreads();
    constexpr int NKC = EE / 32;
    for (int kc = 0; kc < NKC; kc++) {
        if (kc + 1 < NKC) GL(kc + 1);
        COMP(kc & 1);
        if (kc + 1 < NKC) SS((kc + 1) & 1);
        __syncthreads();
    }

    {
        int r = tid >> 1, hi = tid & 1;
        float mk = masks[m0 + r];
        float4 v = *reinterpret_cast<const float4*>(pah + (size_t)(m0 + r) * AD + hi * 4);
        sA[0][r * SAH + hi * 2]     = pack_h2(v.x * mk, v.y * mk);
        sA[0][r * SAH + hi * 2 + 1] = pack_h2(v.z * mk, v.w * mk);
        sA[0][r * SAH + 4 + hi * 2]     = 0u;
        sA[0][r * SAH + 4 + hi * 2 + 1] = 0u;
        float4 w = *reinterpret_cast<const float4*>(wih + (size_t)(n0 + r) * 520 + 512 + hi * 4);
        sB[0][r * SAH + hi * 2]     = pack_h2(w.x, w.y);
        sB[0][r * SAH + hi * 2 + 1] = pack_h2(w.z, w.w);
        sB[0][r * SAH + 4 + hi * 2]     = 0u;
        sB[0][r * SAH + 4 + hi * 2 + 1] = 0u;
        float4 u = *reinterpret_cast<const float4*>(wihp + (size_t)(n0 + r) * AD + hi * 4);
        sB[1][r * SAH + hi * 2]     = pack_h2(u.x, u.y);
        sB[1][r * SAH + hi * 2 + 1] = pack_h2(u.z, u.w);
        sB[1][r * SAH + 4 + hi * 2]     = 0u;
        sB[1][r * SAH + 4 + hi * 2 + 1] = 0u;
    }
    __syncthreads();
    {
        const int ck = (lane & 3);
        unsigned af2[4][4], b0f[4][2], b1f[4][2];
#pragma unroll
        for (int mt = 0; mt < 4; mt++) {
            int r = wm * 64 + mt * 16 + (lane >> 2);
            af2[mt][0] = sA[0][r * SAH + ck];
            af2[mt][1] = sA[0][(r + 8) * SAH + ck];
            af2[mt][2] = sA[0][r * SAH + ck + 4];
            af2[mt][3] = sA[0][(r + 8) * SAH + ck + 4];
        }
#pragma unroll
        for (int nt = 0; nt < 4; nt++) {
            int n = wn * 32 + nt * 8 + (lane >> 2);
            b0f[nt][0] = sB[0][n * SAH + ck]; b0f[nt][1] = sB[0][n * SAH + ck + 4];
            b1f[nt][0] = sB[1][n * SAH + ck]; b1f[nt][1] = sB[1][n * SAH + ck + 4];
        }
#pragma unroll
        for (int mt = 0; mt < 4; mt++)
#pragma unroll
            for (int nt = 0; nt < 4; nt++) {
                mma16h(acc[mt][nt], af2[mt], b0f[nt]);
                float acc2l[4] = {0.f, 0.f, 0.f, 0.f};
                mma16h(acc2l, af2[mt], b1f[nt]);

                int r = m0 + wm * 64 + mt * 16 + (lane >> 2);
                int c = n0 + wn * 32 + nt * 8 + ((lane & 3) << 1);
                float hb0 = (c < 1024) ? bhh[c] : 0.f;
                float hb1 = (c < 1024) ? bhh[c + 1] : 0.f;
                float b0 = bih[c] + hb0, b1 = bih[c + 1] + hb1;
                g_gi16[((size_t)r * H3 + c) >> 1] =
                    pack_h2(acc[mt][nt][0] + b0, acc[mt][nt][1] + b1);
                g_gi16[((size_t)(r + 8) * H3 + c) >> 1] =
                    pack_h2(acc[mt][nt][2] + b0, acc[mt][nt][3] + b1);
                float pb0 = (c < 1024) ? bhhp[c] : 0.f;
                float pb1 = (c < 1024) ? bhhp[c + 1] : 0.f;
                float p0 = bihp[c] + pb0, p1 = bihp[c + 1] + pb1;
                g_gip16[((size_t)r * H3 + c) >> 1] =
                    pack_h2(acc2l[0] + p0, acc2l[1] + p1);
                g_gip16[((size_t)(r + 8) * H3 + c) >> 1] =
                    pack_h2(acc2l[2] + p0, acc2l[3] + p1);
            }
    }
}

// ===========================================================================
// Persistent scan (R15/R16 winner): FP16 K=16 MMA, 8 fully-prefetched stages,
// mbarrier .noinc tracked cp.async. gi read as packed half2.
// ===========================================================================
#define SW_LD 260   // u32 per W row
#define SA_LD 36    // u32 per A chunk row
#define MB_U32 16                           // 8 mbarriers (64 B)
#define SMEM_SCAN ((MB_U32 + 96*SW_LD + 8*64*SA_LD) * 4)

__global__ void __launch_bounds__(256, 1) scan_k(
    const float* __restrict__ whh, const float* __restrict__ whhp,
    const float* __restrict__ masks, const float* __restrict__ ginit,
    const float* __restrict__ bhh, const float* __restrict__ bhhp,
    const float* __restrict__ hxs, const float* __restrict__ hys,
    float* __restrict__ out)
{
    extern __shared__ unsigned sh[];
    unsigned* sW = sh + MB_U32;                 // 96 x 260
    unsigned* sA = sh + MB_U32 + 96 * SW_LD;    // 8 stages x 64 x 36

    unsigned smb;   // shared base address (mbarriers live at offset 0)
    asm("{ .reg .u64 t; cvta.to.shared.u64 t, %1; cvt.u32.u64 %0, t; }"
        : "=r"(smb) : "l"(sh));

    const int bx = blockIdx.x;
    const int p  = bx & 15;
    const int j0 = p * 32;
    const int m0 = ((bx >> 4) & 3) * 64;
    const int cell = bx >> 6;
    const int grp = bx >> 4;

    const float* W  = cell ? whhp : whh;
    const unsigned* gi16 = cell ? g_gip16 : g_gi16;
    const float* bh = cell ? bhhp : bhh;
    const float* hsrc = cell ? hys : hxs;
    float* outs = out + (cell ? (TNH + NH) : 0);
    float* hf   = out + (cell ? (2 * TNH + NH) : TNH);
    unsigned* bcnt = &g_bars[grp].cnt;
    unsigned* bgen = &g_bars[grp].gen;

    const int tid = threadIdx.x, lane = tid & 31, warp = tid >> 5;
    const int wm = warp & 1;
    const int wn = warp >> 1;

    // ---- mbarriers (256 noinc arrivals each per step) ----
    if (tid == 0) {
#pragma unroll
        for (int c = 0; c < 8; c++)
            asm volatile("mbarrier.init.shared.b64 [%0], %1;"
                         :: "r"(smb + c * 8), "r"(256u) : "memory");
    }

    // ---- preload weights into SMEM as fp16 ----
    for (int i = tid; i < 96 * 128; i += 256) {
        int rr = i >> 7;
        int f4 = i & 127;
        int g = rr >> 5, jj = rr & 31;
        float4 v = *reinterpret_cast<const float4*>(W + (size_t)(g * HH + j0 + jj) * HH + f4 * 4);
        sW[rr * SW_LD + f4 * 2]     = pack_h2(v.x, v.y);
        sW[rr * SW_LD + f4 * 2 + 1] = pack_h2(v.z, v.w);
    }

    // ---- init own slice of A(0) (global, half2 words) ----
    for (int idx = tid; idx < 64 * 16; idx += 256) {
        int row = idx >> 4, cp = idx & 15;
        int n = m0 + row, c = j0 + cp * 2;
        float mk = masks[n];
        float2 hv = *reinterpret_cast<const float2*>(hsrc + (size_t)n * HH + c);
        float a0 = hv.x * mk, a1 = hv.y * mk;
        if (cell) {
            float2 gv = *reinterpret_cast<const float2*>(ginit + (size_t)n * HH + c);
            a0 += gv.x * (1.f - mk);
            a1 += gv.y * (1.f - mk);
        }
        g_A16[cell][0][(size_t)n * 256 + (j0 >> 1) + cp] = pack_h2(a0, a1);
    }

    const int cb = j0 + wn * 8 + ((lane & 3) << 1);
    const float2 bn2 = *reinterpret_cast<const float2*>(bh + 2 * HH + cb);
    const unsigned sA_u32 = smb + ((MB_U32 + 96 * SW_LD) << 2);

    // ---- init barrier (publish A(0) slices; also orders mbarrier.init) ----
    {
        __syncthreads();
        if (tid == 0) {
            __threadfence();
            unsigned g0;
            asm volatile("ld.acquire.gpu.u32 %0, [%1];" : "=r"(g0) : "l"(bgen));
            unsigned v = atomicAdd(bcnt, 1u);
            if (v == GSIZE - 1) {
                *bcnt = 0u;
                asm volatile("st.release.gpu.u32 [%0], %1;" :: "l"(bgen), "r"(g0 + 1u));
            } else {
                unsigned cur;
                do { asm volatile("ld.acquire.gpu.u32 %0, [%1];" : "=r"(cur) : "l"(bgen)); }
                while (cur < g0 + 1u);
            }
        }
        __syncthreads();
    }

    // ---- register-carried state hq (fp32) ----
    float2 hq[4];
#pragma unroll
    for (int q = 0; q < 4; q++) {
        int n = m0 + wm * 32 + (q >> 1) * 16 + (lane >> 2) + (q & 1) * 8;
        float mk = masks[n];
        float2 hv = *reinterpret_cast<const float2*>(hsrc + (size_t)n * HH + cb);
        float a0 = hv.x * mk, a1 = hv.y * mk;
        if (cell) {
            float2 gv = *reinterpret_cast<const float2*>(ginit + (size_t)n * HH + cb);
            a0 += gv.x * (1.f - mk);
            a1 += gv.y * (1.f - mk);
        }
        hq[q] = make_float2(a0, a1);
    }

    // ---- initial operand prefetch (gi packed half2) ----
    float2 pir[4], piz[4], pin[4], pg[4];
    float pmask[4];
#pragma unroll
    for (int q = 0; q < 4; q++) {
        int n = m0 + wm * 32 + (q >> 1) * 16 + (lane >> 2) + (q & 1) * 8;
        size_t gb = ((size_t)n * H3 + cb) >> 1;
        pmask[q] = masks[NB + n];
        pir[q] = h2f2(gi16[gb]);
        piz[q] = h2f2(gi16[gb + HH / 2]);
        pin[q] = h2f2(gi16[gb + HH]);
        pg[q] = cell ? *reinterpret_cast<const float2*>(ginit + (size_t)(NB + n) * HH + cb)
                     : make_float2(0.f, 0.f);
    }

    for (int t = 0; t < TT; t++) {
        const int rb = t & 1;
        const unsigned* Ard = g_A16[cell][rb];
        unsigned*       Awr = g_A16[cell][rb ^ 1];
        const size_t trow = (size_t)t * NB;
        const unsigned* As = Ard + (size_t)m0 * 256;
        const unsigned par = (unsigned)(t & 1);

        // ---- issue ALL 8 chunks immediately (max MLP), mbarrier-tracked ----
#pragma unroll
        for (int c = 0; c < 8; c++) {
#pragma unroll
            for (int pp = 0; pp < 2; pp++) {
                int e = tid + pp * 256;
                int row = e >> 3;
                int c4 = (e & 7) << 2;
                unsigned d = sA_u32 + (((c * 64 + row) * SA_LD + c4) << 2);
                const unsigned* src = As + (size_t)row * 256 + c * 32 + c4;
                asm volatile("cp.async.cg.shared.global [%0], [%1], 16;" :: "r"(d), "l"(src));
            }
            asm volatile("cp.async.mbarrier.arrive.noinc.shared.b64 [%0];"
                         :: "r"(smb + c * 8) : "memory");
        }

        float acc[3][2][4];
#pragma unroll
        for (int g = 0; g < 3; g++)
#pragma unroll
            for (int mt = 0; mt < 2; mt++)
#pragma unroll
                for (int q = 0; q < 4; q++) acc[g][mt][q] = 0.f;

        for (int i = 0; i < 8; i++) {
            mbar_wait(smb + i * 8, par);
            const unsigned* sab = sA + i * 64 * SA_LD;
#pragma unroll
            for (int k16 = 0; k16 < 4; k16++) {
                const int ck = k16 * 8 + (lane & 3);
                unsigned af[2][4];
#pragma unroll
                for (int mt = 0; mt < 2; mt++) {
                    int r = wm * 32 + mt * 16 + (lane >> 2);
                    af[mt][0] = sab[r * SA_LD + ck];
                    af[mt][1] = sab[(r + 8) * SA_LD + ck];
                    af[mt][2] = sab[r * SA_LD + ck + 4];
                    af[mt][3] = sab[(r + 8) * SA_LD + ck + 4];
                }
                const int kg = i * 32 + k16 * 8 + (lane & 3);
#pragma unroll
                for (int g = 0; g < 3; g++) {
                    int bn = g * 32 + wn * 8 + (lane >> 2);
                    unsigned bf[2] = { sW[bn * SW_LD + kg], sW[bn * SW_LD + kg + 4] };
#pragma unroll
                    for (int mt = 0; mt < 2; mt++)
                        mma16h(acc[g][mt], af[mt], bf);
                }
            }
        }

        if (t < TT - 1) {
            // ---- gate math; h parked in acc[0], next-A (fp16) to global ----
#pragma unroll
            for (int mt = 0; mt < 2; mt++)
#pragma unroll
                for (int half = 0; half < 2; half++) {
                    int q = mt * 2 + half;
                    int n = m0 + wm * 32 + mt * 16 + (lane >> 2) + half * 8;
                    float mnx = pmask[q];
                    float rr0 = fsig(pir[q].x + acc[0][mt][half * 2]);
                    float rr1 = fsig(pir[q].y + acc[0][mt][half * 2 + 1]);
                    float zz0 = fsig(piz[q].x + acc[1][mt][half * 2]);
                    float zz1 = fsig(piz[q].y + acc[1][mt][half * 2 + 1]);
                    float nn0 = ftanh(pin[q].x + rr0 * (acc[2][mt][half * 2] + bn2.x));
                    float nn1 = ftanh(pin[q].y + rr1 * (acc[2][mt][half * 2 + 1] + bn2.y));
                    float h0 = (1.f - zz0) * nn0 + zz0 * hq[q].x;
                    float h1 = (1.f - zz1) * nn1 + zz1 * hq[q].y;
                    acc[0][mt][half * 2]     = h0;
                    acc[0][mt][half * 2 + 1] = h1;
                    float a0 = h0 * mnx + pg[q].x * (1.f - mnx);
                    float a1 = h1 * mnx + pg[q].y * (1.f - mnx);
                    Awr[(size_t)n * 256 + (cb >> 1)] = pack_h2(a0, a1);
                    hq[q] = make_float2(a0, a1);
                }

            // ---- arrive (non-blocking); syncs also provide stage WAR order ----
            __syncthreads();
            unsigned tgt = 0u;
            if (tid == 0) {
                __threadfence();
                unsigned g0;
                asm volatile("ld.acquire.gpu.u32 %0, [%1];" : "=r"(g0) : "l"(bgen));
                tgt = g0 + 1u;
                unsigned v = atomicAdd(bcnt, 1u);
                if (v == GSIZE - 1) {
                    *bcnt = 0u;
                    asm volatile("st.release.gpu.u32 [%0], %1;" :: "l"(bgen), "r"(tgt));
                }
            }

            // ---- shadow work: outs stores + next-step prefetch ----
#pragma unroll
            for (int mt = 0; mt < 2; mt++)
#pragma unroll
                for (int half = 0; half < 2; half++) {
                    int n = m0 + wm * 32 + mt * 16 + (lane >> 2) + half * 8;
                    *reinterpret_cast<float2*>(outs + (trow + n) * HH + cb) =
                        make_float2(acc[0][mt][half * 2], acc[0][mt][half * 2 + 1]);
                }
            const size_t trow1 = trow + NB;
            const bool hasnext2 = (t + 2 < TT);
#pragma unroll
            for (int q = 0; q < 4; q++) {
                int n = m0 + wm * 32 + (q >> 1) * 16 + (lane >> 2) + (q & 1) * 8;
                size_t gb = ((trow1 + n) * (size_t)H3 + cb) >> 1;
                pmask[q] = hasnext2 ? masks[trow1 + NB + n] : 0.f;
                pir[q] = h2f2(gi16[gb]);
                piz[q] = h2f2(gi16[gb + HH / 2]);
                pin[q] = h2f2(gi16[gb + HH]);
                pg[q] = (cell && hasnext2)
                    ? *reinterpret_cast<const float2*>(
                          ginit + (size_t)(trow1 + NB + n) * HH + cb)
                    : make_float2(0.f, 0.f);
            }

            // ---- wait ----
            if (tid == 0) {
                unsigned cur;
                do { asm volatile("ld.acquire.gpu.u32 %0, [%1];" : "=r"(cur) : "l"(bgen)); }
                while (cur < tgt);
            }
            __syncthreads();
        } else {
            // ---- final step ----
#pragma unroll
            for (int mt = 0; mt < 2; mt++)
#pragma unroll
                for (int half = 0; half < 2; half++) {
                    int q = mt * 2 + half;
                    int n = m0 + wm * 32 + mt * 16 + (lane >> 2) + half * 8;
                    size_t mrow = trow + n;
                    float rr0 = fsig(pir[q].x + acc[0][mt][half * 2]);
                    float rr1 = fsig(pir[q].y + acc[0][mt][half * 2 + 1]);
                    float zz0 = fsig(piz[q].x + acc[1][mt][half * 2]);
                    float zz1 = fsig(piz[q].y + acc[1][mt][half * 2 + 1]);
                    float nn0 = ftanh(pin[q].x + rr0 * (acc[2][mt][half * 2] + bn2.x));
                    float nn1 = ftanh(pin[q].y + rr1 * (acc[2][mt][half * 2 + 1] + bn2.y));
                    float h0 = (1.f - zz0) * nn0 + zz0 * hq[q].x;
                    float h1 = (1.f - zz1) * nn1 + zz1 * hq[q].y;
                    *reinterpret_cast<float2*>(outs + mrow * HH + cb) = make_float2(h0, h1);
                    *reinterpret_cast<float2*>(hf + (size_t)n * HH + cb) = make_float2(h0, h1);
                }
        }
    }
}

extern "C" void kernel_launch(void* const* d_in, const int* in_sizes, int n_in,
                              void* d_out, int out_size)
{
    const float* x     = (const float*)d_in[0];
    const float* hxs   = (const float*)d_in[1];
    const float* hys   = (const float*)d_in[2];
    const float* ginit = (const float*)d_in[3];
    const float* masks = (const float*)d_in[4];
    const float* pah   = (const float*)d_in[5];
    const float* wih   = (const float*)d_in[6];
    const float* whh   = (const float*)d_in[7];
    const float* bih   = (const float*)d_in[8];
    const float* bhh   = (const float*)d_in[9];
    const float* wihp  = (const float*)d_in[10];
    const float* whhp  = (const float*)d_in[11];
    const float* bihp  = (const float*)d_in[12];
    const float* bhhp  = (const float*)d_in[13];
    float* out = (float*)d_out;

    gi_gemm_k<<<dim3(12, 256), 256>>>(x, wih, wihp, pah, masks, bih, bihp, bhh, bhhp);

    cudaFuncSetAttribute(scan_k, cudaFuncAttributeMaxDynamicSharedMemorySize, SMEM_SCAN);
    scan_k<<<NCTA, 256, SMEM_SCAN>>>(whh, whhp, masks, ginit, bhh, bhhp, hxs, hys, out);
}